// round 1
// baseline (speedup 1.0000x reference)
#include <cuda_runtime.h>
#include <math.h>

#define BDIM 32
#define SDIM 256
#define EDIM 768
#define HDIM 32
#define DDIM 24
#define ROWS (BDIM*SDIM)     /* 8192 */
#define QKVN (3*EDIM)        /* 2304 */

// Scratch for fused q|k|v, row-major (8192 x 2304). q pre-scaled by D^-0.5.
__device__ float g_qkv[(size_t)ROWS * QKVN];

// ---------------- QKV GEMM (fp32 SIMT, 128x128x8, 8x8 microtile) ----------------
#define BM 128
#define BN 128
#define BK 8
#define TM 8
#define TN 8

__global__ __launch_bounds__(256) void qkv_gemm_kernel(
    const float* __restrict__ A,
    const float* __restrict__ Wq, const float* __restrict__ Wk, const float* __restrict__ Wv,
    const float* __restrict__ bq, const float* __restrict__ bk, const float* __restrict__ bv)
{
    __shared__ float As[BK][BM + 4];   // +4 pad: conflict-free transpose store
    __shared__ float Bs[BK][BN];

    const int bx = blockIdx.x;            // N tile (0..17)
    const int by = blockIdx.y;            // M tile (0..63)
    const int nbase = bx * BN;
    const int which = nbase / EDIM;       // 0=q 1=k 2=v (BN=128 divides 768)
    const float* __restrict__ W    = (which == 0) ? Wq : ((which == 1) ? Wk : Wv);
    const float* __restrict__ bias = (which == 0) ? bq : ((which == 1) ? bk : bv);
    const int ncol0 = nbase - which * EDIM;
    const float scale = (which == 0) ? 0.20412414523193154f /* 24^-0.5 */ : 1.0f;

    const int tid  = threadIdx.x;
    const int tcol = tid % (BN / TN);     // 0..15
    const int trow = tid / (BN / TN);     // 0..15

    const int arow  = tid >> 1;           // 0..127
    const int acol4 = (tid & 1) * 4;      // 0 or 4
    const int brow  = tid >> 5;           // 0..7
    const int bcol4 = (tid & 31) * 4;     // 0..124

    const float* Abase = A + (size_t)(by * BM) * EDIM;
    const float* Bbase = W + ncol0;

    float acc[TM][TN];
    #pragma unroll
    for (int i = 0; i < TM; i++)
        #pragma unroll
        for (int j = 0; j < TN; j++) acc[i][j] = 0.f;

    for (int k0 = 0; k0 < EDIM; k0 += BK) {
        float4 av = *(const float4*)(Abase + (size_t)arow * EDIM + k0 + acol4);
        As[acol4 + 0][arow] = av.x;
        As[acol4 + 1][arow] = av.y;
        As[acol4 + 2][arow] = av.z;
        As[acol4 + 3][arow] = av.w;
        *(float4*)&Bs[brow][bcol4] =
            *(const float4*)(Bbase + (size_t)(k0 + brow) * EDIM + bcol4);
        __syncthreads();

        #pragma unroll
        for (int kk = 0; kk < BK; kk++) {
            float ar[TM], br[TN];
            #pragma unroll
            for (int i = 0; i < TM; i++) ar[i] = As[kk][trow * TM + i];
            #pragma unroll
            for (int j = 0; j < TN; j++) br[j] = Bs[kk][tcol * TN + j];
            #pragma unroll
            for (int i = 0; i < TM; i++)
                #pragma unroll
                for (int j = 0; j < TN; j++)
                    acc[i][j] += ar[i] * br[j];
        }
        __syncthreads();
    }

    #pragma unroll
    for (int i = 0; i < TM; i++) {
        const int row = by * BM + trow * TM + i;
        float* Cp = g_qkv + (size_t)row * QKVN + nbase + tcol * TN;
        #pragma unroll
        for (int j = 0; j < TN; j += 4) {
            float4 o;
            o.x = (acc[i][j + 0] + bias[ncol0 + tcol * TN + j + 0]) * scale;
            o.y = (acc[i][j + 1] + bias[ncol0 + tcol * TN + j + 1]) * scale;
            o.z = (acc[i][j + 2] + bias[ncol0 + tcol * TN + j + 2]) * scale;
            o.w = (acc[i][j + 3] + bias[ncol0 + tcol * TN + j + 3]) * scale;
            *(float4*)(Cp + j) = o;
        }
    }
}

// ---------------- Fused attention + rotary contraction + output heads ----------------
// out_x[b,s] = sum_t delta[b,s,t,0] * sum_h probs[b,h,s,t] * (v[b,t,h*D..] . Wfx[h*D..])
// One block per (b, 16-row s-tile). 256 threads = one per t column.
#define TS 16

__global__ __launch_bounds__(256) void attn_kernel(
    const float* __restrict__ attn_bias,
    const float* __restrict__ delta,
    const float* __restrict__ Wfx, const float* __restrict__ Wfy, const float* __restrict__ Wfz,
    float* __restrict__ out)
{
    extern __shared__ float sm[];
    float* q_s = sm;                     // TS*768 (q rows, pre-scaled)
    float* wf  = sm + TS * EDIM;         // 3*768
    float* red = wf + 3 * EDIM;          // 3*TS*8

    const int b    = blockIdx.y;
    const int s0   = blockIdx.x * TS;
    const int t    = threadIdx.x;
    const int lane = t & 31;
    const int wid  = t >> 5;

    // Load q tile (coalesced float4)
    for (int i = t; i < TS * (EDIM / 4); i += 256) {
        const int s  = i / (EDIM / 4);
        const int c4 = i % (EDIM / 4);
        ((float4*)q_s)[i] =
            ((const float4*)(g_qkv + (size_t)(b * SDIM + s0 + s) * QKVN))[c4];
    }
    for (int i = t; i < EDIM / 4; i += 256) {
        ((float4*)wf)[i]              = ((const float4*)Wfx)[i];
        ((float4*)(wf + EDIM))[i]     = ((const float4*)Wfy)[i];
        ((float4*)(wf + 2 * EDIM))[i] = ((const float4*)Wfz)[i];
    }
    __syncthreads();

    float accx[TS], accy[TS], accz[TS];
    #pragma unroll
    for (int s = 0; s < TS; s++) { accx[s] = 0.f; accy[s] = 0.f; accz[s] = 0.f; }

    const float* krow = g_qkv + (size_t)(b * SDIM + t) * QKVN + EDIM;
    const float* vrow = krow + EDIM;

    for (int h = 0; h < HDIM; h++) {
        // k[b,t,h,:] into registers (LDG.128 x6, L2-resident)
        float kr[DDIM];
        const float4* kp = (const float4*)(krow + h * DDIM);
        #pragma unroll
        for (int i = 0; i < 6; i++) {
            float4 x = kp[i];
            kr[4*i] = x.x; kr[4*i+1] = x.y; kr[4*i+2] = x.z; kr[4*i+3] = x.w;
        }

        // v projected onto Wfx/Wfy/Wfz for this head -> three scalars
        float vx = 0.f, vy = 0.f, vz = 0.f;
        {
            const float4* vp  = (const float4*)(vrow + h * DDIM);
            const float4* wxp = (const float4*)(wf + h * DDIM);
            const float4* wyp = (const float4*)(wf + EDIM + h * DDIM);
            const float4* wzp = (const float4*)(wf + 2 * EDIM + h * DDIM);
            #pragma unroll
            for (int i = 0; i < 6; i++) {
                float4 vv = vp[i], wx = wxp[i], wy = wyp[i], wz = wzp[i];
                vx += vv.x*wx.x + vv.y*wx.y + vv.z*wx.z + vv.w*wx.w;
                vy += vv.x*wy.x + vv.y*wy.y + vv.z*wy.z + vv.w*wy.w;
                vz += vv.x*wz.x + vv.y*wz.y + vv.z*wz.z + vv.w*wz.w;
            }
        }

        // scores for 16 s rows at column t
        float p[TS];
        const float* bb = attn_bias + (((size_t)b * HDIM + h) * SDIM + s0) * SDIM + t;
        #pragma unroll
        for (int s = 0; s < TS; s++) {
            const float4* q4 = (const float4*)(q_s + s * EDIM + h * DDIM);
            float sc = 0.f;
            #pragma unroll
            for (int i = 0; i < 6; i++) {
                float4 qv = q4[i];
                sc += qv.x*kr[4*i] + qv.y*kr[4*i+1] + qv.z*kr[4*i+2] + qv.w*kr[4*i+3];
            }
            p[s] = sc + bb[(size_t)s * SDIM];
        }

        // row max over 256 t
        #pragma unroll
        for (int s = 0; s < TS; s++) {
            float v = p[s];
            v = fmaxf(v, __shfl_xor_sync(0xffffffffu, v, 16));
            v = fmaxf(v, __shfl_xor_sync(0xffffffffu, v, 8));
            v = fmaxf(v, __shfl_xor_sync(0xffffffffu, v, 4));
            v = fmaxf(v, __shfl_xor_sync(0xffffffffu, v, 2));
            v = fmaxf(v, __shfl_xor_sync(0xffffffffu, v, 1));
            if (lane == 0) red[s * 8 + wid] = v;
        }
        __syncthreads();
        #pragma unroll
        for (int s = 0; s < TS; s++) {
            float m = red[s * 8];
            #pragma unroll
            for (int w = 1; w < 8; w++) m = fmaxf(m, red[s * 8 + w]);
            p[s] = __expf(p[s] - m);
        }
        __syncthreads();
        // row sum
        #pragma unroll
        for (int s = 0; s < TS; s++) {
            float v = p[s];
            v += __shfl_xor_sync(0xffffffffu, v, 16);
            v += __shfl_xor_sync(0xffffffffu, v, 8);
            v += __shfl_xor_sync(0xffffffffu, v, 4);
            v += __shfl_xor_sync(0xffffffffu, v, 2);
            v += __shfl_xor_sync(0xffffffffu, v, 1);
            if (lane == 0) red[s * 8 + wid] = v;
        }
        __syncthreads();
        #pragma unroll
        for (int s = 0; s < TS; s++) {
            float sum = red[s * 8];
            #pragma unroll
            for (int w = 1; w < 8; w++) sum += red[s * 8 + w];
            const float inv = __fdividef(1.0f, sum);
            const float pi = p[s] * inv;
            accx[s] += pi * vx;
            accy[s] += pi * vy;
            accz[s] += pi * vz;
        }
        __syncthreads();   // protect red before next head
    }

    // Finalize: weight by delta_pos and block-reduce over t
    const float* dp = delta + (((size_t)b * SDIM + s0) * SDIM + t) * 3;
    #pragma unroll
    for (int s = 0; s < TS; s++) {
        const float dx = dp[(size_t)s * SDIM * 3 + 0];
        const float dy = dp[(size_t)s * SDIM * 3 + 1];
        const float dz = dp[(size_t)s * SDIM * 3 + 2];
        float vx_ = accx[s] * dx;
        float vy_ = accy[s] * dy;
        float vz_ = accz[s] * dz;
        #pragma unroll
        for (int off = 16; off > 0; off >>= 1) {
            vx_ += __shfl_xor_sync(0xffffffffu, vx_, off);
            vy_ += __shfl_xor_sync(0xffffffffu, vy_, off);
            vz_ += __shfl_xor_sync(0xffffffffu, vz_, off);
        }
        if (lane == 0) {
            red[(0 * TS + s) * 8 + wid] = vx_;
            red[(1 * TS + s) * 8 + wid] = vy_;
            red[(2 * TS + s) * 8 + wid] = vz_;
        }
    }
    __syncthreads();
    if (t < TS * 3) {
        const int s = t / 3, c = t % 3;
        float sum = 0.f;
        #pragma unroll
        for (int w = 0; w < 8; w++) sum += red[(c * TS + s) * 8 + w];
        out[((size_t)(b * SDIM) + s0 + s) * 3 + c] = sum;
    }
}

// ---------------- launch ----------------
extern "C" void kernel_launch(void* const* d_in, const int* in_sizes, int n_in,
                              void* d_out, int out_size)
{
    const float* feats     = (const float*)d_in[0];
    const float* attn_bias = (const float*)d_in[1];
    const float* delta     = (const float*)d_in[2];
    const float* Wq  = (const float*)d_in[3];
    const float* bq  = (const float*)d_in[4];
    const float* Wk  = (const float*)d_in[5];
    const float* bk  = (const float*)d_in[6];
    const float* Wv  = (const float*)d_in[7];
    const float* bv  = (const float*)d_in[8];
    const float* Wfx = (const float*)d_in[9];
    const float* Wfy = (const float*)d_in[10];
    const float* Wfz = (const float*)d_in[11];
    float* out = (float*)d_out;

    dim3 g1(QKVN / BN, ROWS / BM);
    qkv_gemm_kernel<<<g1, 256>>>(feats, Wq, Wk, Wv, bq, bk, bv);

    const size_t smem = (size_t)(TS * EDIM + 3 * EDIM + 3 * TS * 8) * sizeof(float);
    cudaFuncSetAttribute(attn_kernel, cudaFuncAttributeMaxDynamicSharedMemorySize, (int)smem);
    dim3 g2(SDIM / TS, BDIM);
    attn_kernel<<<g2, 256, smem>>>(attn_bias, delta, Wfx, Wfy, Wfz, out);
}

// round 2
// speedup vs baseline: 1.3443x; 1.3443x over previous
#include <cuda_runtime.h>
#include <math.h>

#define BDIM 32
#define SDIM 256
#define EDIM 768
#define HDIM 32
#define DDIM 24
#define ROWS (BDIM*SDIM)     /* 8192 */

// Scratch: q (row-major, pre-scaled), k transposed [b][h][t][d], v row-major,
// vproj [b][h][t][{x,y,z,pad}]
__device__ float g_q [(size_t)ROWS * EDIM];
__device__ float g_kt[(size_t)ROWS * EDIM];
__device__ float g_v [(size_t)ROWS * EDIM];
__device__ float g_vp[(size_t)ROWS * HDIM * 4];

// ---------------- QKV GEMM (fp32 SIMT, 128x128x8, 8x8 microtile) ----------------
#define BM 128
#define BN 128
#define BK 8
#define TM 8
#define TN 8

__global__ __launch_bounds__(256) void qkv_gemm_kernel(
    const float* __restrict__ A,
    const float* __restrict__ Wq, const float* __restrict__ Wk, const float* __restrict__ Wv,
    const float* __restrict__ bq, const float* __restrict__ bk, const float* __restrict__ bv)
{
    __shared__ float As[BK][BM + 4];
    __shared__ float Bs[BK][BN];

    const int bx = blockIdx.x;            // N tile (0..17)
    const int by = blockIdx.y;            // M tile (0..63)
    const int nbase = bx * BN;
    const int which = nbase / EDIM;       // 0=q 1=k 2=v
    const float* __restrict__ W    = (which == 0) ? Wq : ((which == 1) ? Wk : Wv);
    const float* __restrict__ bias = (which == 0) ? bq : ((which == 1) ? bk : bv);
    const int ncol0 = nbase - which * EDIM;
    const float scale = (which == 0) ? 0.20412414523193154f /* 24^-0.5 */ : 1.0f;

    const int tid  = threadIdx.x;
    const int tcol = tid % (BN / TN);
    const int trow = tid / (BN / TN);

    const int arow  = tid >> 1;
    const int acol4 = (tid & 1) * 4;
    const int brow  = tid >> 5;
    const int bcol4 = (tid & 31) * 4;

    const float* Abase = A + (size_t)(by * BM) * EDIM;
    const float* Bbase = W + ncol0;

    float acc[TM][TN];
    #pragma unroll
    for (int i = 0; i < TM; i++)
        #pragma unroll
        for (int j = 0; j < TN; j++) acc[i][j] = 0.f;

    for (int k0 = 0; k0 < EDIM; k0 += BK) {
        float4 av = *(const float4*)(Abase + (size_t)arow * EDIM + k0 + acol4);
        As[acol4 + 0][arow] = av.x;
        As[acol4 + 1][arow] = av.y;
        As[acol4 + 2][arow] = av.z;
        As[acol4 + 3][arow] = av.w;
        *(float4*)&Bs[brow][bcol4] =
            *(const float4*)(Bbase + (size_t)(k0 + brow) * EDIM + bcol4);
        __syncthreads();

        #pragma unroll
        for (int kk = 0; kk < BK; kk++) {
            float ar[TM], br[TN];
            #pragma unroll
            for (int i = 0; i < TM; i++) ar[i] = As[kk][trow * TM + i];
            #pragma unroll
            for (int j = 0; j < TN; j++) br[j] = Bs[kk][tcol * TN + j];
            #pragma unroll
            for (int i = 0; i < TM; i++)
                #pragma unroll
                for (int j = 0; j < TN; j++)
                    acc[i][j] += ar[i] * br[j];
        }
        __syncthreads();
    }

    #pragma unroll
    for (int i = 0; i < TM; i++) {
        const int row = by * BM + trow * TM + i;
        #pragma unroll
        for (int j = 0; j < TN; j += 4) {
            const int c0 = ncol0 + tcol * TN + j;
            float4 o;
            o.x = (acc[i][j + 0] + bias[c0 + 0]) * scale;
            o.y = (acc[i][j + 1] + bias[c0 + 1]) * scale;
            o.z = (acc[i][j + 2] + bias[c0 + 2]) * scale;
            o.w = (acc[i][j + 3] + bias[c0 + 3]) * scale;
            if (which == 0) {
                *(float4*)&g_q[(size_t)row * EDIM + c0] = o;
            } else if (which == 2) {
                *(float4*)&g_v[(size_t)row * EDIM + c0] = o;
            } else {
                const int bb = row >> 8, t = row & 255;
                const int h = c0 / DDIM, d = c0 - h * DDIM;   // 4-col group never crosses head
                *(float4*)&g_kt[((size_t)(bb * HDIM + h) * SDIM + t) * DDIM + d] = o;
            }
        }
    }
}

// ---------------- vproj: vproj[b,h,t,c] = v[b,t,h,:].Wf_c[h,:] ----------------
__global__ __launch_bounds__(256) void vproj_kernel(
    const float* __restrict__ Wfx, const float* __restrict__ Wfy, const float* __restrict__ Wfz)
{
    const int row = blockIdx.x * 8 + (threadIdx.x >> 5);   // 0..8191 (= b*256+t)
    const int h   = threadIdx.x & 31;
    const float* v  = g_v + (size_t)row * EDIM + h * DDIM;
    const float* wx = Wfx + h * DDIM;
    const float* wy = Wfy + h * DDIM;
    const float* wz = Wfz + h * DDIM;
    float vx = 0.f, vy = 0.f, vz = 0.f;
    #pragma unroll
    for (int i = 0; i < 6; i++) {
        float4 vv = *(const float4*)(v  + 4 * i);
        float4 ax = *(const float4*)(wx + 4 * i);
        float4 ay = *(const float4*)(wy + 4 * i);
        float4 az = *(const float4*)(wz + 4 * i);
        vx += vv.x*ax.x + vv.y*ax.y + vv.z*ax.z + vv.w*ax.w;
        vy += vv.x*ay.x + vv.y*ay.y + vv.z*ay.z + vv.w*ay.w;
        vz += vv.x*az.x + vv.y*az.y + vv.z*az.z + vv.w*az.w;
    }
    const int b = row >> 8, t = row & 255;
    *(float4*)&g_vp[((size_t)(b * HDIM + h) * SDIM + t) * 4] = make_float4(vx, vy, vz, 0.f);
}

// ---------------- Fused attention ----------------
// Block: (b, 16-s-row tile). 8 warps; warp owns 2 s rows; lane owns 8 t columns.
#define TS 16

__global__ __launch_bounds__(256, 2) void attn_kernel(
    const float* __restrict__ attn_bias,
    const float* __restrict__ delta,
    float* __restrict__ out)
{
    extern __shared__ float sm[];
    float* ds = sm;                       // TS*256*4 floats (delta, padded)
    float* kh = sm + TS * SDIM * 4;       // 256*28 floats (k tile, padded rows)

    const int b    = blockIdx.y;
    const int s0   = blockIdx.x * TS;
    const int tid  = threadIdx.x;
    const int lane = tid & 31;
    const int wid  = tid >> 5;
    const int r0   = 2 * wid;

    // Stage delta tile (contiguous region), repack stride 3 -> 4
    {
        const float* dsrc = delta + (size_t)(b * SDIM + s0) * SDIM * 3;
        for (int i = tid; i < TS * SDIM * 3; i += 256) {
            const int st = i / 3, c = i - st * 3;
            ds[st * 4 + c] = dsrc[i];
        }
    }

    float ox0 = 0.f, oy0 = 0.f, oz0 = 0.f, ox1 = 0.f, oy1 = 0.f, oz1 = 0.f;

    const size_t qbase0 = (size_t)(b * SDIM + s0 + r0) * EDIM;
    const float* ds0 = ds + (r0)     * SDIM * 4;
    const float* ds1 = ds + (r0 + 1) * SDIM * 4;

    for (int h = 0; h < HDIM; h++) {
        __syncthreads();   // protect previous kh (also orders delta staging on h=0)
        {
            const float4* slab = (const float4*)(g_kt + (size_t)(b * HDIM + h) * SDIM * DDIM);
            #pragma unroll
            for (int i = 0; i < 6; i++) {
                const int idx = tid + i * 256;
                const int t = idx / 6, c = idx - t * 6;
                *(float4*)&kh[t * 28 + c * 4] = slab[idx];
            }
        }
        __syncthreads();

        // q rows into registers (broadcast loads, L1-hit)
        float q0[24], q1[24];
        {
            const float4* qp0 = (const float4*)(g_q + qbase0 + h * DDIM);
            const float4* qp1 = (const float4*)(g_q + qbase0 + EDIM + h * DDIM);
            #pragma unroll
            for (int i = 0; i < 6; i++) {
                float4 a = qp0[i];
                q0[4*i] = a.x; q0[4*i+1] = a.y; q0[4*i+2] = a.z; q0[4*i+3] = a.w;
                float4 c = qp1[i];
                q1[4*i] = c.x; q1[4*i+1] = c.y; q1[4*i+2] = c.z; q1[4*i+3] = c.w;
            }
        }

        float Z0 = 0.f, Sx0 = 0.f, Sy0 = 0.f, Sz0 = 0.f;
        float Z1 = 0.f, Sx1 = 0.f, Sy1 = 0.f, Sz1 = 0.f;
        const float* bb0 = attn_bias + (((size_t)b * HDIM + h) * SDIM + s0 + r0) * SDIM;
        const float* bb1 = bb0 + SDIM;
        const float4* vp = (const float4*)(g_vp + (size_t)(b * HDIM + h) * SDIM * 4);

        #pragma unroll 4
        for (int j = 0; j < 8; j++) {
            const int t = lane + 32 * j;
            const float* kp = &kh[t * 28];
            float sa0 = 0.f, sb0 = 0.f, sa1 = 0.f, sb1 = 0.f;
            #pragma unroll
            for (int i = 0; i < 6; i++) {
                float4 kv = *(const float4*)(kp + 4 * i);
                sa0 = fmaf(q0[4*i+0], kv.x, sa0); sb0 = fmaf(q0[4*i+1], kv.y, sb0);
                sa0 = fmaf(q0[4*i+2], kv.z, sa0); sb0 = fmaf(q0[4*i+3], kv.w, sb0);
                sa1 = fmaf(q1[4*i+0], kv.x, sa1); sb1 = fmaf(q1[4*i+1], kv.y, sb1);
                sa1 = fmaf(q1[4*i+2], kv.z, sa1); sb1 = fmaf(q1[4*i+3], kv.w, sb1);
            }
            const float sc0 = sa0 + sb0 + bb0[t];
            const float sc1 = sa1 + sb1 + bb1[t];
            const float p0 = __expf(sc0);
            const float p1 = __expf(sc1);
            const float4 vv = vp[t];
            Z0 += p0; Z1 += p1;
            const float4 d0 = *(const float4*)&ds0[t * 4];
            const float4 d1 = *(const float4*)&ds1[t * 4];
            Sx0 = fmaf(p0 * vv.x, d0.x, Sx0);
            Sy0 = fmaf(p0 * vv.y, d0.y, Sy0);
            Sz0 = fmaf(p0 * vv.z, d0.z, Sz0);
            Sx1 = fmaf(p1 * vv.x, d1.x, Sx1);
            Sy1 = fmaf(p1 * vv.y, d1.y, Sy1);
            Sz1 = fmaf(p1 * vv.z, d1.z, Sz1);
        }

        // warp-local reductions over t
        #pragma unroll
        for (int off = 16; off > 0; off >>= 1) {
            Z0  += __shfl_xor_sync(0xffffffffu, Z0,  off);
            Sx0 += __shfl_xor_sync(0xffffffffu, Sx0, off);
            Sy0 += __shfl_xor_sync(0xffffffffu, Sy0, off);
            Sz0 += __shfl_xor_sync(0xffffffffu, Sz0, off);
            Z1  += __shfl_xor_sync(0xffffffffu, Z1,  off);
            Sx1 += __shfl_xor_sync(0xffffffffu, Sx1, off);
            Sy1 += __shfl_xor_sync(0xffffffffu, Sy1, off);
            Sz1 += __shfl_xor_sync(0xffffffffu, Sz1, off);
        }
        const float inv0 = __fdividef(1.f, Z0);
        const float inv1 = __fdividef(1.f, Z1);
        ox0 = fmaf(Sx0, inv0, ox0); oy0 = fmaf(Sy0, inv0, oy0); oz0 = fmaf(Sz0, inv0, oz0);
        ox1 = fmaf(Sx1, inv1, ox1); oy1 = fmaf(Sy1, inv1, oy1); oz1 = fmaf(Sz1, inv1, oz1);
    }

    if (lane == 0) {
        const size_t o0 = (size_t)(b * SDIM + s0 + r0) * 3;
        out[o0 + 0] = ox0; out[o0 + 1] = oy0; out[o0 + 2] = oz0;
        out[o0 + 3] = ox1; out[o0 + 4] = oy1; out[o0 + 5] = oz1;
    }
}

// ---------------- launch ----------------
extern "C" void kernel_launch(void* const* d_in, const int* in_sizes, int n_in,
                              void* d_out, int out_size)
{
    const float* feats     = (const float*)d_in[0];
    const float* attn_bias = (const float*)d_in[1];
    const float* delta     = (const float*)d_in[2];
    const float* Wq  = (const float*)d_in[3];
    const float* bq  = (const float*)d_in[4];
    const float* Wk  = (const float*)d_in[5];
    const float* bk  = (const float*)d_in[6];
    const float* Wv  = (const float*)d_in[7];
    const float* bv  = (const float*)d_in[8];
    const float* Wfx = (const float*)d_in[9];
    const float* Wfy = (const float*)d_in[10];
    const float* Wfz = (const float*)d_in[11];
    float* out = (float*)d_out;

    dim3 g1(3 * EDIM / BN, ROWS / BM);
    qkv_gemm_kernel<<<g1, 256>>>(feats, Wq, Wk, Wv, bq, bk, bv);

    vproj_kernel<<<ROWS / 8, 256>>>(Wfx, Wfy, Wfz);

    const size_t smem = (size_t)(TS * SDIM * 4 + SDIM * 28) * sizeof(float);  // 92 KB
    static int attr_set = -1;
    cudaFuncSetAttribute(attn_kernel, cudaFuncAttributeMaxDynamicSharedMemorySize, (int)smem);
    (void)attr_set;
    dim3 g2(SDIM / TS, BDIM);
    attn_kernel<<<g2, 256, smem>>>(attn_bias, delta, out);
}

// round 4
// speedup vs baseline: 2.2741x; 1.6917x over previous
#include <cuda_runtime.h>
#include <cuda_bf16.h>
#include <cstdint>
#include <math.h>

#define BDIM 32
#define SDIM 256
#define EDIM 768
#define HDIM 32
#define DDIM 24
#define ROWS (BDIM*SDIM)     /* 8192 */
#define QKVN (3*EDIM)        /* 2304 */

// ---------------- device scratch ----------------
__device__ __align__(16) __nv_bfloat16 g_a_hi[(size_t)ROWS * EDIM];
__device__ __align__(16) __nv_bfloat16 g_a_lo[(size_t)ROWS * EDIM];
__device__ __align__(16) __nv_bfloat16 g_b_hi[(size_t)QKVN * EDIM];   // wt[n][k]
__device__ __align__(16) __nv_bfloat16 g_b_lo[(size_t)QKVN * EDIM];
__device__ float g_q [(size_t)ROWS * EDIM];
__device__ float g_kt[(size_t)ROWS * EDIM];
__device__ float g_v [(size_t)ROWS * EDIM];
__device__ float g_vp[(size_t)ROWS * HDIM * 4];

// ---------------- PTX helpers (base sm_80+ ISA only — no 'a' features) ----------------
__device__ __forceinline__ uint32_t smem_to_u32(const void* p) {
    uint32_t a;
    asm("{ .reg .u64 t; cvta.to.shared.u64 t, %1; cvt.u32.u64 %0, t; }" : "=r"(a) : "l"(p));
    return a;
}
__device__ __forceinline__ void cp_async16(uint32_t s, const void* g) {
    asm volatile("cp.async.cg.shared.global [%0], [%1], 16;" :: "r"(s), "l"(g) : "memory");
}
__device__ __forceinline__ void ldsm4(uint32_t* r, uint32_t addr) {
    asm volatile("ldmatrix.sync.aligned.m8n8.x4.shared.b16 {%0,%1,%2,%3}, [%4];"
                 : "=r"(r[0]), "=r"(r[1]), "=r"(r[2]), "=r"(r[3]) : "r"(addr));
}
__device__ __forceinline__ void mma16816(float* c, const uint32_t* a, const uint32_t* b) {
    asm volatile("mma.sync.aligned.m16n8k16.row.col.f32.bf16.bf16.f32 "
                 "{%0,%1,%2,%3}, {%4,%5,%6,%7}, {%8,%9}, {%0,%1,%2,%3};"
                 : "+f"(c[0]), "+f"(c[1]), "+f"(c[2]), "+f"(c[3])
                 : "r"(a[0]), "r"(a[1]), "r"(a[2]), "r"(a[3]), "r"(b[0]), "r"(b[1]));
}

// ---------------- prep: feats -> bf16 hi/lo ----------------
__global__ __launch_bounds__(256) void prep_a_kernel(const float* __restrict__ feats)
{
    const size_t i = (size_t)blockIdx.x * 256 + threadIdx.x;    // float4 index
    float4 v = ((const float4*)feats)[i];
    __nv_bfloat16 hx = __float2bfloat16(v.x), hy = __float2bfloat16(v.y);
    __nv_bfloat16 hz = __float2bfloat16(v.z), hw = __float2bfloat16(v.w);
    __nv_bfloat16 lx = __float2bfloat16(v.x - __bfloat162float(hx));
    __nv_bfloat16 ly = __float2bfloat16(v.y - __bfloat162float(hy));
    __nv_bfloat16 lz = __float2bfloat16(v.z - __bfloat162float(hz));
    __nv_bfloat16 lw = __float2bfloat16(v.w - __bfloat162float(hw));
    __nv_bfloat162* ph = (__nv_bfloat162*)g_a_hi;
    __nv_bfloat162* pl = (__nv_bfloat162*)g_a_lo;
    ph[2*i]   = __nv_bfloat162(hx, hy); ph[2*i+1] = __nv_bfloat162(hz, hw);
    pl[2*i]   = __nv_bfloat162(lx, ly); pl[2*i+1] = __nv_bfloat162(lz, lw);
}

// ---------------- prep: weights transpose + split ----------------
__global__ __launch_bounds__(256) void prep_w_kernel(
    const float* __restrict__ Wq, const float* __restrict__ Wk, const float* __restrict__ Wv)
{
    __shared__ float tile[32][33];
    const int which = blockIdx.z;
    const float* W = (which == 0) ? Wq : ((which == 1) ? Wk : Wv);
    const int n0 = blockIdx.x * 32, k0 = blockIdx.y * 32;
    const int tx = threadIdx.x & 31, ty = (threadIdx.x >> 5) * 4;
    #pragma unroll
    for (int i = 0; i < 4; i++)
        tile[ty + i][tx] = W[(size_t)(k0 + ty + i) * EDIM + n0 + tx];
    __syncthreads();
    #pragma unroll
    for (int i = 0; i < 4; i++) {
        const int n = n0 + ty + i, k = k0 + tx;
        const float v = tile[tx][ty + i];
        __nv_bfloat16 h = __float2bfloat16(v);
        __nv_bfloat16 l = __float2bfloat16(v - __bfloat162float(h));
        g_b_hi[(size_t)(which * EDIM + n) * EDIM + k] = h;
        g_b_lo[(size_t)(which * EDIM + n) * EDIM + k] = l;
    }
}

// ---------------- HMMA QKV GEMM: 128x128 block, K chunks of 32, double buffer ----------------
// smem stage: Ahi(8K) Alo(8K) Bhi(8K) Blo(8K) = 32KB; x2 = 64KB
#define OFF_AHI 0
#define OFF_ALO 8192
#define OFF_BHI 16384
#define OFF_BLO 24576
#define STG 32768
#define GEMM_SMEM (2*STG)
#define NCHUNK (EDIM/32)   /* 24 */

// tile row = 64B (32 bf16), 4 x 16B chunks; swizzle c' = c ^ ((row>>1)&3)
__device__ __forceinline__ uint32_t sw_addr(uint32_t tile, int row, int kc) {
    return tile + (row << 6) + ((kc ^ ((row >> 1) & 3)) << 4);
}

__global__ __launch_bounds__(256, 1) void qkv_mma_kernel(
    const float* __restrict__ bq, const float* __restrict__ bk, const float* __restrict__ bv)
{
    extern __shared__ char smem[];
    const uint32_t smem_base = smem_to_u32(smem);
    const int tid  = threadIdx.x;
    const int wid  = tid >> 5;
    const int lane = tid & 31;
    const int m0    = blockIdx.y * 128;
    const int nbase = blockIdx.x * 128;

    const int wm = wid & 1, wn = wid >> 1;     // warp tile 64(m) x 32(n)
    const int mw = wm * 64, nw = wn * 32;
    const int lane7 = lane & 7, quad = lane >> 3;

    float c[4][4][4];
    #pragma unroll
    for (int i = 0; i < 4; i++)
        #pragma unroll
        for (int j = 0; j < 4; j++)
            #pragma unroll
            for (int r = 0; r < 4; r++) c[i][j][r] = 0.f;

    // ---- async stage copy ----
    auto copy_stage = [&](int s) {
        const uint32_t sb = smem_base + (s & 1) * STG;
        const int k0 = s * 32;
        #pragma unroll
        for (int i = 0; i < 2; i++) {
            const int idx = tid + i * 256;         // 0..511
            const int row = idx >> 2, cc = idx & 3;
            const uint32_t soff = (row << 6) + ((cc ^ ((row >> 1) & 3)) << 4);
            const size_t ga = (size_t)(m0 + row) * EDIM + k0 + cc * 8;
            const size_t gb = (size_t)(nbase + row) * EDIM + k0 + cc * 8;
            cp_async16(sb + OFF_AHI + soff, g_a_hi + ga);
            cp_async16(sb + OFF_ALO + soff, g_a_lo + ga);
            cp_async16(sb + OFF_BHI + soff, g_b_hi + gb);
            cp_async16(sb + OFF_BLO + soff, g_b_lo + gb);
        }
        asm volatile("cp.async.commit_group;" ::: "memory");
    };

    copy_stage(0);

    for (int ch = 0; ch < NCHUNK; ch++) {
        if (ch + 1 < NCHUNK) {
            copy_stage(ch + 1);
            asm volatile("cp.async.wait_group 1;" ::: "memory");
        } else {
            asm volatile("cp.async.wait_group 0;" ::: "memory");
        }
        __syncthreads();

        const uint32_t sb = smem_base + (ch & 1) * STG;
        #pragma unroll
        for (int ks = 0; ks < 2; ks++) {
            uint32_t bh[4][2], bl[4][2], a[4][4];
            // B fragments: 2 x ldmatrix.x4 per operand cover n=32
            #pragma unroll
            for (int j2 = 0; j2 < 2; j2++) {
                const int rowB = nw + j2 * 16 + ((quad >> 1) << 3) + lane7;
                const int kcB  = 2 * ks + (quad & 1);
                uint32_t r[4];
                ldsm4(r, sw_addr(sb + OFF_BHI, rowB, kcB));
                bh[2*j2][0] = r[0]; bh[2*j2][1] = r[1];
                bh[2*j2+1][0] = r[2]; bh[2*j2+1][1] = r[3];
                ldsm4(r, sw_addr(sb + OFF_BLO, rowB, kcB));
                bl[2*j2][0] = r[0]; bl[2*j2][1] = r[1];
                bl[2*j2+1][0] = r[2]; bl[2*j2+1][1] = r[3];
            }
            const int rowA_ = ((quad & 1) << 3) + lane7;
            const int kcA   = 2 * ks + (quad >> 1);
            #pragma unroll
            for (int i = 0; i < 4; i++)
                ldsm4(a[i], sw_addr(sb + OFF_AHI, mw + 16 * i + rowA_, kcA));
            #pragma unroll
            for (int i = 0; i < 4; i++)
                #pragma unroll
                for (int j = 0; j < 4; j++) {
                    mma16816(c[i][j], a[i], bh[j]);   // Ahi*Bhi
                    mma16816(c[i][j], a[i], bl[j]);   // Ahi*Blo
                }
            #pragma unroll
            for (int i = 0; i < 4; i++)
                ldsm4(a[i], sw_addr(sb + OFF_ALO, mw + 16 * i + rowA_, kcA));
            #pragma unroll
            for (int i = 0; i < 4; i++)
                #pragma unroll
                for (int j = 0; j < 4; j++)
                    mma16816(c[i][j], a[i], bh[j]);   // Alo*Bhi
        }
        __syncthreads();
    }

    // ---- epilogue: bias + scale, scatter to g_q / g_kt(transposed) / g_v ----
    const int which = blockIdx.x / 6;
    const int ncol_off = which * EDIM;
    const float* bias = (which == 0) ? bq : ((which == 1) ? bk : bv);
    const float scale = (which == 0) ? 0.20412414523193154f : 1.0f;
    const int g  = lane >> 2;
    const int t4 = lane & 3;

    #pragma unroll
    for (int i = 0; i < 4; i++) {
        #pragma unroll
        for (int half = 0; half < 2; half++) {
            const int row = m0 + mw + 16 * i + g + 8 * half;
            const int bb = row >> 8, tt = row & 255;
            #pragma unroll
            for (int j = 0; j < 4; j++) {
                const int col = nbase + nw + 8 * j + 2 * t4 - ncol_off;
                float2 v;
                v.x = (c[i][j][2*half + 0] + bias[col])     * scale;
                v.y = (c[i][j][2*half + 1] + bias[col + 1]) * scale;
                if (which == 0) {
                    *(float2*)&g_q[(size_t)row * EDIM + col] = v;
                } else if (which == 2) {
                    *(float2*)&g_v[(size_t)row * EDIM + col] = v;
                } else {
                    const int h = col / DDIM, d = col - h * DDIM;
                    *(float2*)&g_kt[((size_t)(bb * HDIM + h) * SDIM + tt) * DDIM + d] = v;
                }
            }
        }
    }
}

// ---------------- vproj ----------------
__global__ __launch_bounds__(256) void vproj_kernel(
    const float* __restrict__ Wfx, const float* __restrict__ Wfy, const float* __restrict__ Wfz)
{
    const int row = blockIdx.x * 8 + (threadIdx.x >> 5);
    const int h   = threadIdx.x & 31;
    const float* v  = g_v + (size_t)row * EDIM + h * DDIM;
    const float* wx = Wfx + h * DDIM;
    const float* wy = Wfy + h * DDIM;
    const float* wz = Wfz + h * DDIM;
    float vx = 0.f, vy = 0.f, vz = 0.f;
    #pragma unroll
    for (int i = 0; i < 6; i++) {
        float4 vv = *(const float4*)(v  + 4 * i);
        float4 ax = *(const float4*)(wx + 4 * i);
        float4 ay = *(const float4*)(wy + 4 * i);
        float4 az = *(const float4*)(wz + 4 * i);
        vx += vv.x*ax.x + vv.y*ax.y + vv.z*ax.z + vv.w*ax.w;
        vy += vv.x*ay.x + vv.y*ay.y + vv.z*ay.z + vv.w*ay.w;
        vz += vv.x*az.x + vv.y*az.y + vv.z*az.z + vv.w*az.w;
    }
    const int b = row >> 8, t = row & 255;
    *(float4*)&g_vp[((size_t)(b * HDIM + h) * SDIM + t) * 4] = make_float4(vx, vy, vz, 0.f);
}

// ---------------- Fused attention ----------------
#define TS 16

__global__ __launch_bounds__(256, 2) void attn_kernel(
    const float* __restrict__ attn_bias,
    const float* __restrict__ delta,
    float* __restrict__ out)
{
    extern __shared__ float sm[];
    float* ds = sm;
    float* kh = sm + TS * SDIM * 4;

    const int b    = blockIdx.y;
    const int s0   = blockIdx.x * TS;
    const int tid  = threadIdx.x;
    const int lane = tid & 31;
    const int wid  = tid >> 5;
    const int r0   = 2 * wid;

    {
        const float* dsrc = delta + (size_t)(b * SDIM + s0) * SDIM * 3;
        for (int i = tid; i < TS * SDIM * 3; i += 256) {
            const int st = i / 3, c = i - st * 3;
            ds[st * 4 + c] = dsrc[i];
        }
    }

    float ox0 = 0.f, oy0 = 0.f, oz0 = 0.f, ox1 = 0.f, oy1 = 0.f, oz1 = 0.f;

    const size_t qbase0 = (size_t)(b * SDIM + s0 + r0) * EDIM;
    const float* ds0 = ds + (r0)     * SDIM * 4;
    const float* ds1 = ds + (r0 + 1) * SDIM * 4;

    for (int h = 0; h < HDIM; h++) {
        __syncthreads();
        {
            const float4* slab = (const float4*)(g_kt + (size_t)(b * HDIM + h) * SDIM * DDIM);
            #pragma unroll
            for (int i = 0; i < 6; i++) {
                const int idx = tid + i * 256;
                const int t = idx / 6, c = idx - t * 6;
                *(float4*)&kh[t * 28 + c * 4] = slab[idx];
            }
        }
        __syncthreads();

        float q0[24], q1[24];
        {
            const float4* qp0 = (const float4*)(g_q + qbase0 + h * DDIM);
            const float4* qp1 = (const float4*)(g_q + qbase0 + EDIM + h * DDIM);
            #pragma unroll
            for (int i = 0; i < 6; i++) {
                float4 a = qp0[i];
                q0[4*i] = a.x; q0[4*i+1] = a.y; q0[4*i+2] = a.z; q0[4*i+3] = a.w;
                float4 c2 = qp1[i];
                q1[4*i] = c2.x; q1[4*i+1] = c2.y; q1[4*i+2] = c2.z; q1[4*i+3] = c2.w;
            }
        }

        float Z0 = 0.f, Sx0 = 0.f, Sy0 = 0.f, Sz0 = 0.f;
        float Z1 = 0.f, Sx1 = 0.f, Sy1 = 0.f, Sz1 = 0.f;
        const float* bb0 = attn_bias + (((size_t)b * HDIM + h) * SDIM + s0 + r0) * SDIM;
        const float* bb1 = bb0 + SDIM;
        const float4* vp = (const float4*)(g_vp + (size_t)(b * HDIM + h) * SDIM * 4);

        #pragma unroll 4
        for (int j = 0; j < 8; j++) {
            const int t = lane + 32 * j;
            const float* kp = &kh[t * 28];
            float sa0 = 0.f, sb0 = 0.f, sa1 = 0.f, sb1 = 0.f;
            #pragma unroll
            for (int i = 0; i < 6; i++) {
                float4 kv = *(const float4*)(kp + 4 * i);
                sa0 = fmaf(q0[4*i+0], kv.x, sa0); sb0 = fmaf(q0[4*i+1], kv.y, sb0);
                sa0 = fmaf(q0[4*i+2], kv.z, sa0); sb0 = fmaf(q0[4*i+3], kv.w, sb0);
                sa1 = fmaf(q1[4*i+0], kv.x, sa1); sb1 = fmaf(q1[4*i+1], kv.y, sb1);
                sa1 = fmaf(q1[4*i+2], kv.z, sa1); sb1 = fmaf(q1[4*i+3], kv.w, sb1);
            }
            const float sc0 = sa0 + sb0 + bb0[t];
            const float sc1 = sa1 + sb1 + bb1[t];
            const float p0 = __expf(sc0);
            const float p1 = __expf(sc1);
            const float4 vv = vp[t];
            Z0 += p0; Z1 += p1;
            const float4 d0 = *(const float4*)&ds0[t * 4];
            const float4 d1 = *(const float4*)&ds1[t * 4];
            Sx0 = fmaf(p0 * vv.x, d0.x, Sx0);
            Sy0 = fmaf(p0 * vv.y, d0.y, Sy0);
            Sz0 = fmaf(p0 * vv.z, d0.z, Sz0);
            Sx1 = fmaf(p1 * vv.x, d1.x, Sx1);
            Sy1 = fmaf(p1 * vv.y, d1.y, Sy1);
            Sz1 = fmaf(p1 * vv.z, d1.z, Sz1);
        }

        #pragma unroll
        for (int off = 16; off > 0; off >>= 1) {
            Z0  += __shfl_xor_sync(0xffffffffu, Z0,  off);
            Sx0 += __shfl_xor_sync(0xffffffffu, Sx0, off);
            Sy0 += __shfl_xor_sync(0xffffffffu, Sy0, off);
            Sz0 += __shfl_xor_sync(0xffffffffu, Sz0, off);
            Z1  += __shfl_xor_sync(0xffffffffu, Z1,  off);
            Sx1 += __shfl_xor_sync(0xffffffffu, Sx1, off);
            Sy1 += __shfl_xor_sync(0xffffffffu, Sy1, off);
            Sz1 += __shfl_xor_sync(0xffffffffu, Sz1, off);
        }
        const float inv0 = __fdividef(1.f, Z0);
        const float inv1 = __fdividef(1.f, Z1);
        ox0 = fmaf(Sx0, inv0, ox0); oy0 = fmaf(Sy0, inv0, oy0); oz0 = fmaf(Sz0, inv0, oz0);
        ox1 = fmaf(Sx1, inv1, ox1); oy1 = fmaf(Sy1, inv1, oy1); oz1 = fmaf(Sz1, inv1, oz1);
    }

    if (lane == 0) {
        const size_t o0 = (size_t)(b * SDIM + s0 + r0) * 3;
        out[o0 + 0] = ox0; out[o0 + 1] = oy0; out[o0 + 2] = oz0;
        out[o0 + 3] = ox1; out[o0 + 4] = oy1; out[o0 + 5] = oz1;
    }
}

// ---------------- launch ----------------
extern "C" void kernel_launch(void* const* d_in, const int* in_sizes, int n_in,
                              void* d_out, int out_size)
{
    const float* feats     = (const float*)d_in[0];
    const float* attn_bias = (const float*)d_in[1];
    const float* delta     = (const float*)d_in[2];
    const float* Wq  = (const float*)d_in[3];
    const float* bq  = (const float*)d_in[4];
    const float* Wk  = (const float*)d_in[5];
    const float* bk  = (const float*)d_in[6];
    const float* Wv  = (const float*)d_in[7];
    const float* bv  = (const float*)d_in[8];
    const float* Wfx = (const float*)d_in[9];
    const float* Wfy = (const float*)d_in[10];
    const float* Wfz = (const float*)d_in[11];
    float* out = (float*)d_out;

    prep_a_kernel<<<(ROWS * EDIM / 4) / 256, 256>>>(feats);
    prep_w_kernel<<<dim3(EDIM / 32, EDIM / 32, 3), 256>>>(Wq, Wk, Wv);

    cudaFuncSetAttribute(qkv_mma_kernel, cudaFuncAttributeMaxDynamicSharedMemorySize, GEMM_SMEM);
    dim3 gg(QKVN / 128, ROWS / 128);   // (18, 64)
    qkv_mma_kernel<<<gg, 256, GEMM_SMEM>>>(bq, bk, bv);

    vproj_kernel<<<ROWS / 8, 256>>>(Wfx, Wfy, Wfz);

    const size_t smem = (size_t)(TS * SDIM * 4 + SDIM * 28) * sizeof(float);
    cudaFuncSetAttribute(attn_kernel, cudaFuncAttributeMaxDynamicSharedMemorySize, (int)smem);
    dim3 g2(SDIM / TS, BDIM);
    attn_kernel<<<g2, 256, smem>>>(attn_bias, delta, out);
}

// round 5
// speedup vs baseline: 2.6966x; 1.1858x over previous
#include <cuda_runtime.h>
#include <cuda_bf16.h>
#include <cstdint>
#include <math.h>

#define BDIM 32
#define SDIM 256
#define EDIM 768
#define HDIM 32
#define DDIM 24
#define ROWS (BDIM*SDIM)     /* 8192 */
#define QKVN (3*EDIM)        /* 2304 */

// ---------------- device scratch ----------------
__device__ __align__(16) __nv_bfloat16 g_a_hi[(size_t)ROWS * EDIM];
__device__ __align__(16) __nv_bfloat16 g_a_lo[(size_t)ROWS * EDIM];
__device__ __align__(16) __nv_bfloat16 g_b_hi[(size_t)QKVN * EDIM];   // wt[n][k]
__device__ __align__(16) __nv_bfloat16 g_b_lo[(size_t)QKVN * EDIM];
__device__ float g_q [(size_t)ROWS * EDIM];
__device__ float g_kt[(size_t)ROWS * EDIM];
__device__ float g_v [(size_t)ROWS * EDIM];
__device__ float g_vp[(size_t)ROWS * HDIM * 4];

// ---------------- PTX helpers (base sm_80+ ISA only) ----------------
__device__ __forceinline__ uint32_t smem_to_u32(const void* p) {
    uint32_t a;
    asm("{ .reg .u64 t; cvta.to.shared.u64 t, %1; cvt.u32.u64 %0, t; }" : "=r"(a) : "l"(p));
    return a;
}
__device__ __forceinline__ void cp_async16(uint32_t s, const void* g) {
    asm volatile("cp.async.cg.shared.global [%0], [%1], 16;" :: "r"(s), "l"(g) : "memory");
}
__device__ __forceinline__ void ldsm4(uint32_t* r, uint32_t addr) {
    asm volatile("ldmatrix.sync.aligned.m8n8.x4.shared.b16 {%0,%1,%2,%3}, [%4];"
                 : "=r"(r[0]), "=r"(r[1]), "=r"(r[2]), "=r"(r[3]) : "r"(addr));
}
__device__ __forceinline__ void mma16816(float* c, const uint32_t* a, const uint32_t* b) {
    asm volatile("mma.sync.aligned.m16n8k16.row.col.f32.bf16.bf16.f32 "
                 "{%0,%1,%2,%3}, {%4,%5,%6,%7}, {%8,%9}, {%0,%1,%2,%3};"
                 : "+f"(c[0]), "+f"(c[1]), "+f"(c[2]), "+f"(c[3])
                 : "r"(a[0]), "r"(a[1]), "r"(a[2]), "r"(a[3]), "r"(b[0]), "r"(b[1]));
}
__device__ __forceinline__ uint32_t pack2(float a, float b) {
    __nv_bfloat162 h = __floats2bfloat162_rn(a, b);
    return *(uint32_t*)&h;
}

// ---------------- prep: feats -> bf16 hi/lo ----------------
__global__ __launch_bounds__(256) void prep_a_kernel(const float* __restrict__ feats)
{
    const size_t i = (size_t)blockIdx.x * 256 + threadIdx.x;
    float4 v = ((const float4*)feats)[i];
    __nv_bfloat16 hx = __float2bfloat16(v.x), hy = __float2bfloat16(v.y);
    __nv_bfloat16 hz = __float2bfloat16(v.z), hw = __float2bfloat16(v.w);
    __nv_bfloat16 lx = __float2bfloat16(v.x - __bfloat162float(hx));
    __nv_bfloat16 ly = __float2bfloat16(v.y - __bfloat162float(hy));
    __nv_bfloat16 lz = __float2bfloat16(v.z - __bfloat162float(hz));
    __nv_bfloat16 lw = __float2bfloat16(v.w - __bfloat162float(hw));
    __nv_bfloat162* ph = (__nv_bfloat162*)g_a_hi;
    __nv_bfloat162* pl = (__nv_bfloat162*)g_a_lo;
    ph[2*i]   = __nv_bfloat162(hx, hy); ph[2*i+1] = __nv_bfloat162(hz, hw);
    pl[2*i]   = __nv_bfloat162(lx, ly); pl[2*i+1] = __nv_bfloat162(lz, lw);
}

// ---------------- prep: weights transpose + split ----------------
__global__ __launch_bounds__(256) void prep_w_kernel(
    const float* __restrict__ Wq, const float* __restrict__ Wk, const float* __restrict__ Wv)
{
    __shared__ float tile[32][33];
    const int which = blockIdx.z;
    const float* W = (which == 0) ? Wq : ((which == 1) ? Wk : Wv);
    const int n0 = blockIdx.x * 32, k0 = blockIdx.y * 32;
    const int tx = threadIdx.x & 31, ty = (threadIdx.x >> 5) * 4;
    #pragma unroll
    for (int i = 0; i < 4; i++)
        tile[ty + i][tx] = W[(size_t)(k0 + ty + i) * EDIM + n0 + tx];
    __syncthreads();
    #pragma unroll
    for (int i = 0; i < 4; i++) {
        const int n = n0 + ty + i, k = k0 + tx;
        const float v = tile[tx][ty + i];
        __nv_bfloat16 h = __float2bfloat16(v);
        __nv_bfloat16 l = __float2bfloat16(v - __bfloat162float(h));
        g_b_hi[(size_t)(which * EDIM + n) * EDIM + k] = h;
        g_b_lo[(size_t)(which * EDIM + n) * EDIM + k] = l;
    }
}

// ---------------- HMMA QKV GEMM (unchanged from round 4) ----------------
#define OFF_AHI 0
#define OFF_ALO 8192
#define OFF_BHI 16384
#define OFF_BLO 24576
#define STG 32768
#define GEMM_SMEM (2*STG)
#define NCHUNK (EDIM/32)

__device__ __forceinline__ uint32_t sw_addr(uint32_t tile, int row, int kc) {
    return tile + (row << 6) + ((kc ^ ((row >> 1) & 3)) << 4);
}

__global__ __launch_bounds__(256, 1) void qkv_mma_kernel(
    const float* __restrict__ bq, const float* __restrict__ bk, const float* __restrict__ bv)
{
    extern __shared__ char smem[];
    const uint32_t smem_base = smem_to_u32(smem);
    const int tid  = threadIdx.x;
    const int wid  = tid >> 5;
    const int lane = tid & 31;
    const int m0    = blockIdx.y * 128;
    const int nbase = blockIdx.x * 128;

    const int wm = wid & 1, wn = wid >> 1;
    const int mw = wm * 64, nw = wn * 32;
    const int lane7 = lane & 7, quad = lane >> 3;

    float c[4][4][4];
    #pragma unroll
    for (int i = 0; i < 4; i++)
        #pragma unroll
        for (int j = 0; j < 4; j++)
            #pragma unroll
            for (int r = 0; r < 4; r++) c[i][j][r] = 0.f;

    auto copy_stage = [&](int s) {
        const uint32_t sb = smem_base + (s & 1) * STG;
        const int k0 = s * 32;
        #pragma unroll
        for (int i = 0; i < 2; i++) {
            const int idx = tid + i * 256;
            const int row = idx >> 2, cc = idx & 3;
            const uint32_t soff = (row << 6) + ((cc ^ ((row >> 1) & 3)) << 4);
            const size_t ga = (size_t)(m0 + row) * EDIM + k0 + cc * 8;
            const size_t gb = (size_t)(nbase + row) * EDIM + k0 + cc * 8;
            cp_async16(sb + OFF_AHI + soff, g_a_hi + ga);
            cp_async16(sb + OFF_ALO + soff, g_a_lo + ga);
            cp_async16(sb + OFF_BHI + soff, g_b_hi + gb);
            cp_async16(sb + OFF_BLO + soff, g_b_lo + gb);
        }
        asm volatile("cp.async.commit_group;" ::: "memory");
    };

    copy_stage(0);

    for (int ch = 0; ch < NCHUNK; ch++) {
        if (ch + 1 < NCHUNK) {
            copy_stage(ch + 1);
            asm volatile("cp.async.wait_group 1;" ::: "memory");
        } else {
            asm volatile("cp.async.wait_group 0;" ::: "memory");
        }
        __syncthreads();

        const uint32_t sb = smem_base + (ch & 1) * STG;
        #pragma unroll
        for (int ks = 0; ks < 2; ks++) {
            uint32_t bh[4][2], bl[4][2], a[4][4];
            #pragma unroll
            for (int j2 = 0; j2 < 2; j2++) {
                const int rowB = nw + j2 * 16 + ((quad >> 1) << 3) + lane7;
                const int kcB  = 2 * ks + (quad & 1);
                uint32_t r[4];
                ldsm4(r, sw_addr(sb + OFF_BHI, rowB, kcB));
                bh[2*j2][0] = r[0]; bh[2*j2][1] = r[1];
                bh[2*j2+1][0] = r[2]; bh[2*j2+1][1] = r[3];
                ldsm4(r, sw_addr(sb + OFF_BLO, rowB, kcB));
                bl[2*j2][0] = r[0]; bl[2*j2][1] = r[1];
                bl[2*j2+1][0] = r[2]; bl[2*j2+1][1] = r[3];
            }
            const int rowA_ = ((quad & 1) << 3) + lane7;
            const int kcA   = 2 * ks + (quad >> 1);
            #pragma unroll
            for (int i = 0; i < 4; i++)
                ldsm4(a[i], sw_addr(sb + OFF_AHI, mw + 16 * i + rowA_, kcA));
            #pragma unroll
            for (int i = 0; i < 4; i++)
                #pragma unroll
                for (int j = 0; j < 4; j++) {
                    mma16816(c[i][j], a[i], bh[j]);
                    mma16816(c[i][j], a[i], bl[j]);
                }
            #pragma unroll
            for (int i = 0; i < 4; i++)
                ldsm4(a[i], sw_addr(sb + OFF_ALO, mw + 16 * i + rowA_, kcA));
            #pragma unroll
            for (int i = 0; i < 4; i++)
                #pragma unroll
                for (int j = 0; j < 4; j++)
                    mma16816(c[i][j], a[i], bh[j]);
        }
        __syncthreads();
    }

    const int which = blockIdx.x / 6;
    const int ncol_off = which * EDIM;
    const float* bias = (which == 0) ? bq : ((which == 1) ? bk : bv);
    const float scale = (which == 0) ? 0.20412414523193154f : 1.0f;
    const int g  = lane >> 2;
    const int t4 = lane & 3;

    #pragma unroll
    for (int i = 0; i < 4; i++) {
        #pragma unroll
        for (int half = 0; half < 2; half++) {
            const int row = m0 + mw + 16 * i + g + 8 * half;
            const int bb = row >> 8, tt = row & 255;
            #pragma unroll
            for (int j = 0; j < 4; j++) {
                const int col = nbase + nw + 8 * j + 2 * t4 - ncol_off;
                float2 v;
                v.x = (c[i][j][2*half + 0] + bias[col])     * scale;
                v.y = (c[i][j][2*half + 1] + bias[col + 1]) * scale;
                if (which == 0) {
                    *(float2*)&g_q[(size_t)row * EDIM + col] = v;
                } else if (which == 2) {
                    *(float2*)&g_v[(size_t)row * EDIM + col] = v;
                } else {
                    const int h = col / DDIM, d = col - h * DDIM;
                    *(float2*)&g_kt[((size_t)(bb * HDIM + h) * SDIM + tt) * DDIM + d] = v;
                }
            }
        }
    }
}

// ---------------- vproj ----------------
__global__ __launch_bounds__(256) void vproj_kernel(
    const float* __restrict__ Wfx, const float* __restrict__ Wfy, const float* __restrict__ Wfz)
{
    const int row = blockIdx.x * 8 + (threadIdx.x >> 5);
    const int h   = threadIdx.x & 31;
    const float* v  = g_v + (size_t)row * EDIM + h * DDIM;
    const float* wx = Wfx + h * DDIM;
    const float* wy = Wfy + h * DDIM;
    const float* wz = Wfz + h * DDIM;
    float vx = 0.f, vy = 0.f, vz = 0.f;
    #pragma unroll
    for (int i = 0; i < 6; i++) {
        float4 vv = *(const float4*)(v  + 4 * i);
        float4 ax = *(const float4*)(wx + 4 * i);
        float4 ay = *(const float4*)(wy + 4 * i);
        float4 az = *(const float4*)(wz + 4 * i);
        vx += vv.x*ax.x + vv.y*ax.y + vv.z*ax.z + vv.w*ax.w;
        vy += vv.x*ay.x + vv.y*ay.y + vv.z*ay.z + vv.w*ay.w;
        vz += vv.x*az.x + vv.y*az.y + vv.z*az.z + vv.w*az.w;
    }
    const int b = row >> 8, t = row & 255;
    *(float4*)&g_vp[((size_t)(b * HDIM + h) * SDIM + t) * 4] = make_float4(vx, vy, vz, 0.f);
}

// ---------------- MMA attention ----------------
// Block = (b, 32 s-rows); 512 threads / 16 warps. Warp: mh=wid&1 (16 s-rows),
// band=wid>>1 (32 t-cols). Per head: S = q@k^T via bf16 hi/lo MMA, softmax and
// G accumulation fully in C-fragment layout.
#define AKT_HI 0
#define AKT_LO 20480
#define AQ_HI  40960
#define AQ_LO  43520
#define AVP    46080    /* 2 x 4096 */
#define AZP    54272    /* 2 x 1024 */
#define ARED   56320    /* 3072 */
#define ATTN_SMEM 59392

__global__ __launch_bounds__(512, 1) void attn_kernel(
    const float* __restrict__ attn_bias,
    const float* __restrict__ delta,
    float* __restrict__ out)
{
    extern __shared__ char sa[];
    const uint32_t sb = smem_to_u32(sa);
    const int b   = blockIdx.y;
    const int s0  = blockIdx.x * 32;
    const int tid = threadIdx.x;
    const int lane = tid & 31;
    const int wid  = tid >> 5;
    const int mh   = wid & 1;
    const int band = wid >> 1;
    const int nb   = band * 32;
    const int g    = lane >> 2;
    const int t4   = lane & 3;

    float G[2][4][2][3];
    #pragma unroll
    for (int r = 0; r < 2; r++)
        #pragma unroll
        for (int j = 0; j < 4; j++)
            #pragma unroll
            for (int cc = 0; cc < 2; cc++)
                #pragma unroll
                for (int x = 0; x < 3; x++) G[r][j][cc][x] = 0.f;

    for (int h = 0; h < HDIM; h++) {
        const int par = h & 1;
        // ---- stage phase ----
        if (tid < 256) {
            // k row tid: 24 fp32 -> bf16 hi/lo, 80B row stride, zero pad
            const float4* kr = (const float4*)(g_kt + ((size_t)(b * HDIM + h) * SDIM + tid) * DDIM);
            uint32_t hw[12], lw[12];
            #pragma unroll
            for (int i = 0; i < 6; i++) {
                float4 v = kr[i];
                float hx = __bfloat162float(__float2bfloat16(v.x));
                float hy = __bfloat162float(__float2bfloat16(v.y));
                float hz = __bfloat162float(__float2bfloat16(v.z));
                float hwv = __bfloat162float(__float2bfloat16(v.w));
                hw[2*i]   = pack2(hx, hy);
                hw[2*i+1] = pack2(hz, hwv);
                lw[2*i]   = pack2(v.x - hx, v.y - hy);
                lw[2*i+1] = pack2(v.z - hz, v.w - hwv);
            }
            char* khp = sa + AKT_HI + tid * 80;
            char* klp = sa + AKT_LO + tid * 80;
            #pragma unroll
            for (int i = 0; i < 3; i++) {
                *(uint4*)(khp + 16*i) = make_uint4(hw[4*i], hw[4*i+1], hw[4*i+2], hw[4*i+3]);
                *(uint4*)(klp + 16*i) = make_uint4(lw[4*i], lw[4*i+1], lw[4*i+2], lw[4*i+3]);
            }
            *(uint4*)(khp + 48) = make_uint4(0,0,0,0);
            *(uint4*)(klp + 48) = make_uint4(0,0,0,0);
        } else {
            const int u = tid - 256;
            if (u < 192) {
                const int idx = u * 4;
                const int r = idx / DDIM, d = idx - r * DDIM;
                float4 v = *(const float4*)(g_q + (size_t)(b * SDIM + s0 + r) * EDIM + h * DDIM + d);
                float hx = __bfloat162float(__float2bfloat16(v.x));
                float hy = __bfloat162float(__float2bfloat16(v.y));
                float hz = __bfloat162float(__float2bfloat16(v.z));
                float hwv = __bfloat162float(__float2bfloat16(v.w));
                *(uint2*)(sa + AQ_HI + r * 80 + d * 2) = make_uint2(pack2(hx, hy), pack2(hz, hwv));
                *(uint2*)(sa + AQ_LO + r * 80 + d * 2) =
                    make_uint2(pack2(v.x - hx, v.y - hy), pack2(v.z - hz, v.w - hwv));
            } else if (u < 224) {
                const int r = u - 192;
                *(uint4*)(sa + AQ_HI + r * 80 + 48) = make_uint4(0,0,0,0);
                *(uint4*)(sa + AQ_LO + r * 80 + 48) = make_uint4(0,0,0,0);
            }
            // vp stage (all 256 upper threads): element u covers t = u
            float4 pv = *(const float4*)(g_vp + ((size_t)(b * HDIM + h) * SDIM + u) * 4);
            *(float4*)(sa + AVP + par * 4096 + u * 16) = pv;
        }
        __syncthreads();

        // ---- MMA phase ----
        const int l16 = lane & 15, lh = lane >> 4;
        uint32_t ah[2][4], al[2][4];
        {
            const uint32_t abase = sb + AQ_HI + (mh * 16 + l16) * 80 + lh * 16;
            ldsm4(ah[0], abase);
            ldsm4(ah[1], abase + 32);
            const uint32_t abl = sb + AQ_LO + (mh * 16 + l16) * 80 + lh * 16;
            ldsm4(al[0], abl);
            ldsm4(al[1], abl + 32);
        }
        float c[4][4];
        #pragma unroll
        for (int j = 0; j < 4; j++)
            #pragma unroll
            for (int r = 0; r < 4; r++) c[j][r] = 0.f;

        const int l8 = lane & 7, l8h = lane >> 3;
        #pragma unroll
        for (int j = 0; j < 4; j++) {
            uint32_t bh[4], bl[4];
            const int rowB = nb + j * 8 + l8;
            ldsm4(bh, sb + AKT_HI + rowB * 80 + l8h * 16);
            ldsm4(bl, sb + AKT_LO + rowB * 80 + l8h * 16);
            mma16816(c[j], ah[0], bh);
            mma16816(c[j], ah[1], bh + 2);
            mma16816(c[j], ah[0], bl);
            mma16816(c[j], ah[1], bl + 2);
            mma16816(c[j], al[0], bh);
            mma16816(c[j], al[1], bh + 2);
        }

        // ---- bias + exp + row partial sums ----
        const float* bp0 = attn_bias +
            (((size_t)b * HDIM + h) * SDIM + s0 + mh * 16 + g) * SDIM + nb + 2 * t4;
        const float* bp1 = bp0 + 8 * SDIM;
        float ps0 = 0.f, ps1 = 0.f;
        #pragma unroll
        for (int j = 0; j < 4; j++) {
            float2 b0 = *(const float2*)(bp0 + 8 * j);
            float2 b1 = *(const float2*)(bp1 + 8 * j);
            c[j][0] = __expf(c[j][0] + b0.x);
            c[j][1] = __expf(c[j][1] + b0.y);
            c[j][2] = __expf(c[j][2] + b1.x);
            c[j][3] = __expf(c[j][3] + b1.y);
            ps0 += c[j][0] + c[j][1];
            ps1 += c[j][2] + c[j][3];
        }
        ps0 += __shfl_xor_sync(0xffffffffu, ps0, 1);
        ps0 += __shfl_xor_sync(0xffffffffu, ps0, 2);
        ps1 += __shfl_xor_sync(0xffffffffu, ps1, 1);
        ps1 += __shfl_xor_sync(0xffffffffu, ps1, 2);
        float* zp = (float*)(sa + AZP + par * 1024);
        if (t4 == 0) {
            zp[(mh * 16 + g) * 8 + band]     = ps0;
            zp[(mh * 16 + g + 8) * 8 + band] = ps1;
        }
        __syncthreads();

        float Z0 = 0.f, Z1 = 0.f;
        {
            float4 a0 = *(float4*)(zp + (mh * 16 + g) * 8);
            float4 a1 = *(float4*)(zp + (mh * 16 + g) * 8 + 4);
            Z0 = (a0.x + a0.y) + (a0.z + a0.w) + (a1.x + a1.y) + (a1.z + a1.w);
            float4 b0 = *(float4*)(zp + (mh * 16 + g + 8) * 8);
            float4 b1 = *(float4*)(zp + (mh * 16 + g + 8) * 8 + 4);
            Z1 = (b0.x + b0.y) + (b0.z + b0.w) + (b1.x + b1.y) + (b1.z + b1.w);
        }
        const float iz0 = __fdividef(1.f, Z0);
        const float iz1 = __fdividef(1.f, Z1);

        // ---- accumulate G ----
        #pragma unroll
        for (int j = 0; j < 4; j++) {
            const char* vpp = sa + AVP + par * 4096 + (nb + 8 * j + 2 * t4) * 16;
            float4 v0 = *(const float4*)vpp;
            float4 v1 = *(const float4*)(vpp + 16);
            const float p00 = c[j][0] * iz0, p01 = c[j][1] * iz0;
            const float p10 = c[j][2] * iz1, p11 = c[j][3] * iz1;
            G[0][j][0][0] = fmaf(p00, v0.x, G[0][j][0][0]);
            G[0][j][0][1] = fmaf(p00, v0.y, G[0][j][0][1]);
            G[0][j][0][2] = fmaf(p00, v0.z, G[0][j][0][2]);
            G[0][j][1][0] = fmaf(p01, v1.x, G[0][j][1][0]);
            G[0][j][1][1] = fmaf(p01, v1.y, G[0][j][1][1]);
            G[0][j][1][2] = fmaf(p01, v1.z, G[0][j][1][2]);
            G[1][j][0][0] = fmaf(p10, v0.x, G[1][j][0][0]);
            G[1][j][0][1] = fmaf(p10, v0.y, G[1][j][0][1]);
            G[1][j][0][2] = fmaf(p10, v0.z, G[1][j][0][2]);
            G[1][j][1][0] = fmaf(p11, v1.x, G[1][j][1][0]);
            G[1][j][1][1] = fmaf(p11, v1.y, G[1][j][1][1]);
            G[1][j][1][2] = fmaf(p11, v1.z, G[1][j][1][2]);
        }
    }

    // ---- delta contraction + output ----
    float ox[2] = {0.f, 0.f}, oy[2] = {0.f, 0.f}, oz[2] = {0.f, 0.f};
    #pragma unroll
    for (int rh = 0; rh < 2; rh++) {
        const int srow = s0 + mh * 16 + g + 8 * rh;
        const float* dp = delta + (size_t)(b * SDIM + srow) * SDIM * 3;
        #pragma unroll
        for (int j = 0; j < 4; j++) {
            const int t0 = nb + 8 * j + 2 * t4;
            const float* d0 = dp + t0 * 3;
            ox[rh] += G[rh][j][0][0] * d0[0] + G[rh][j][1][0] * d0[3];
            oy[rh] += G[rh][j][0][1] * d0[1] + G[rh][j][1][1] * d0[4];
            oz[rh] += G[rh][j][0][2] * d0[2] + G[rh][j][1][2] * d0[5];
        }
    }
    #pragma unroll
    for (int rh = 0; rh < 2; rh++) {
        ox[rh] += __shfl_xor_sync(0xffffffffu, ox[rh], 1);
        ox[rh] += __shfl_xor_sync(0xffffffffu, ox[rh], 2);
        oy[rh] += __shfl_xor_sync(0xffffffffu, oy[rh], 1);
        oy[rh] += __shfl_xor_sync(0xffffffffu, oy[rh], 2);
        oz[rh] += __shfl_xor_sync(0xffffffffu, oz[rh], 1);
        oz[rh] += __shfl_xor_sync(0xffffffffu, oz[rh], 2);
    }
    float* red = (float*)(sa + ARED);
    if (t4 == 0) {
        #pragma unroll
        for (int rh = 0; rh < 2; rh++) {
            const int row = mh * 16 + g + 8 * rh;
            red[(row * 8 + band) * 3 + 0] = ox[rh];
            red[(row * 8 + band) * 3 + 1] = oy[rh];
            red[(row * 8 + band) * 3 + 2] = oz[rh];
        }
    }
    __syncthreads();
    if (tid < 96) {
        const int row = tid / 3, x = tid % 3;
        float s = 0.f;
        #pragma unroll
        for (int k = 0; k < 8; k++) s += red[(row * 8 + k) * 3 + x];
        out[((size_t)(b * SDIM) + s0 + row) * 3 + x] = s;
    }
}

// ---------------- launch ----------------
extern "C" void kernel_launch(void* const* d_in, const int* in_sizes, int n_in,
                              void* d_out, int out_size)
{
    const float* feats     = (const float*)d_in[0];
    const float* attn_bias = (const float*)d_in[1];
    const float* delta     = (const float*)d_in[2];
    const float* Wq  = (const float*)d_in[3];
    const float* bq  = (const float*)d_in[4];
    const float* Wk  = (const float*)d_in[5];
    const float* bk  = (const float*)d_in[6];
    const float* Wv  = (const float*)d_in[7];
    const float* bv  = (const float*)d_in[8];
    const float* Wfx = (const float*)d_in[9];
    const float* Wfy = (const float*)d_in[10];
    const float* Wfz = (const float*)d_in[11];
    float* out = (float*)d_out;

    prep_a_kernel<<<(ROWS * EDIM / 4) / 256, 256>>>(feats);
    prep_w_kernel<<<dim3(EDIM / 32, EDIM / 32, 3), 256>>>(Wq, Wk, Wv);

    cudaFuncSetAttribute(qkv_mma_kernel, cudaFuncAttributeMaxDynamicSharedMemorySize, GEMM_SMEM);
    dim3 gg(QKVN / 128, ROWS / 128);
    qkv_mma_kernel<<<gg, 256, GEMM_SMEM>>>(bq, bk, bv);

    vproj_kernel<<<ROWS / 8, 256>>>(Wfx, Wfy, Wfz);

    cudaFuncSetAttribute(attn_kernel, cudaFuncAttributeMaxDynamicSharedMemorySize, ATTN_SMEM);
    dim3 g2(SDIM / 32, BDIM);
    attn_kernel<<<g2, 512, ATTN_SMEM>>>(attn_bias, delta, out);
}

// round 6
// speedup vs baseline: 2.7187x; 1.0082x over previous
#include <cuda_runtime.h>
#include <cuda_bf16.h>
#include <cstdint>
#include <math.h>

#define BDIM 32
#define SDIM 256
#define EDIM 768
#define HDIM 32
#define DDIM 24
#define ROWS (BDIM*SDIM)     /* 8192 */
#define QKVN (3*EDIM)        /* 2304 */

// ---------------- device scratch ----------------
__device__ __align__(16) __nv_bfloat16 g_a_hi[(size_t)ROWS * EDIM];
__device__ __align__(16) __nv_bfloat16 g_a_lo[(size_t)ROWS * EDIM];
__device__ __align__(16) __nv_bfloat16 g_b_hi[(size_t)QKVN * EDIM];   // wt[n][k]
__device__ __align__(16) __nv_bfloat16 g_b_lo[(size_t)QKVN * EDIM];
// q/k in attn-ready packed bf16 hi/lo: [b][h][s][32] (cols 24..31 stay zero)
__device__ __align__(16) __nv_bfloat16 g_qh[(size_t)ROWS * HDIM * 32];
__device__ __align__(16) __nv_bfloat16 g_ql[(size_t)ROWS * HDIM * 32];
__device__ __align__(16) __nv_bfloat16 g_kh[(size_t)ROWS * HDIM * 32];
__device__ __align__(16) __nv_bfloat16 g_kl[(size_t)ROWS * HDIM * 32];
__device__ float g_v [(size_t)ROWS * EDIM];
__device__ float g_vp[(size_t)ROWS * HDIM * 4];

// ---------------- PTX helpers (base sm_80+ ISA only) ----------------
__device__ __forceinline__ uint32_t smem_to_u32(const void* p) {
    uint32_t a;
    asm("{ .reg .u64 t; cvta.to.shared.u64 t, %1; cvt.u32.u64 %0, t; }" : "=r"(a) : "l"(p));
    return a;
}
__device__ __forceinline__ void cp_async16(uint32_t s, const void* g) {
    asm volatile("cp.async.cg.shared.global [%0], [%1], 16;" :: "r"(s), "l"(g) : "memory");
}
__device__ __forceinline__ void ldsm4(uint32_t* r, uint32_t addr) {
    asm volatile("ldmatrix.sync.aligned.m8n8.x4.shared.b16 {%0,%1,%2,%3}, [%4];"
                 : "=r"(r[0]), "=r"(r[1]), "=r"(r[2]), "=r"(r[3]) : "r"(addr));
}
__device__ __forceinline__ void mma16816(float* c, const uint32_t* a, const uint32_t* b) {
    asm volatile("mma.sync.aligned.m16n8k16.row.col.f32.bf16.bf16.f32 "
                 "{%0,%1,%2,%3}, {%4,%5,%6,%7}, {%8,%9}, {%0,%1,%2,%3};"
                 : "+f"(c[0]), "+f"(c[1]), "+f"(c[2]), "+f"(c[3])
                 : "r"(a[0]), "r"(a[1]), "r"(a[2]), "r"(a[3]), "r"(b[0]), "r"(b[1]));
}

// ---------------- prep: feats -> bf16 hi/lo ----------------
__global__ __launch_bounds__(256) void prep_a_kernel(const float* __restrict__ feats)
{
    const size_t i = (size_t)blockIdx.x * 256 + threadIdx.x;
    float4 v = ((const float4*)feats)[i];
    __nv_bfloat16 hx = __float2bfloat16(v.x), hy = __float2bfloat16(v.y);
    __nv_bfloat16 hz = __float2bfloat16(v.z), hw = __float2bfloat16(v.w);
    __nv_bfloat16 lx = __float2bfloat16(v.x - __bfloat162float(hx));
    __nv_bfloat16 ly = __float2bfloat16(v.y - __bfloat162float(hy));
    __nv_bfloat16 lz = __float2bfloat16(v.z - __bfloat162float(hz));
    __nv_bfloat16 lw = __float2bfloat16(v.w - __bfloat162float(hw));
    __nv_bfloat162* ph = (__nv_bfloat162*)g_a_hi;
    __nv_bfloat162* pl = (__nv_bfloat162*)g_a_lo;
    ph[2*i]   = __nv_bfloat162(hx, hy); ph[2*i+1] = __nv_bfloat162(hz, hw);
    pl[2*i]   = __nv_bfloat162(lx, ly); pl[2*i+1] = __nv_bfloat162(lz, lw);
}

// ---------------- prep: weights transpose + split ----------------
__global__ __launch_bounds__(256) void prep_w_kernel(
    const float* __restrict__ Wq, const float* __restrict__ Wk, const float* __restrict__ Wv)
{
    __shared__ float tile[32][33];
    const int which = blockIdx.z;
    const float* W = (which == 0) ? Wq : ((which == 1) ? Wk : Wv);
    const int n0 = blockIdx.x * 32, k0 = blockIdx.y * 32;
    const int tx = threadIdx.x & 31, ty = (threadIdx.x >> 5) * 4;
    #pragma unroll
    for (int i = 0; i < 4; i++)
        tile[ty + i][tx] = W[(size_t)(k0 + ty + i) * EDIM + n0 + tx];
    __syncthreads();
    #pragma unroll
    for (int i = 0; i < 4; i++) {
        const int n = n0 + ty + i, k = k0 + tx;
        const float v = tile[tx][ty + i];
        __nv_bfloat16 h = __float2bfloat16(v);
        __nv_bfloat16 l = __float2bfloat16(v - __bfloat162float(h));
        g_b_hi[(size_t)(which * EDIM + n) * EDIM + k] = h;
        g_b_lo[(size_t)(which * EDIM + n) * EDIM + k] = l;
    }
}

// ---------------- HMMA QKV GEMM ----------------
#define OFF_AHI 0
#define OFF_ALO 8192
#define OFF_BHI 16384
#define OFF_BLO 24576
#define STG 32768
#define GEMM_SMEM (2*STG)
#define NCHUNK (EDIM/32)

__device__ __forceinline__ uint32_t sw_addr(uint32_t tile, int row, int kc) {
    return tile + (row << 6) + ((kc ^ ((row >> 1) & 3)) << 4);
}

__global__ __launch_bounds__(256, 1) void qkv_mma_kernel(
    const float* __restrict__ bq, const float* __restrict__ bk, const float* __restrict__ bv)
{
    extern __shared__ char smem[];
    const uint32_t smem_base = smem_to_u32(smem);
    const int tid  = threadIdx.x;
    const int wid  = tid >> 5;
    const int lane = tid & 31;
    const int m0    = blockIdx.y * 128;
    const int nbase = blockIdx.x * 128;

    const int wm = wid & 1, wn = wid >> 1;
    const int mw = wm * 64, nw = wn * 32;
    const int lane7 = lane & 7, quad = lane >> 3;

    float c[4][4][4];
    #pragma unroll
    for (int i = 0; i < 4; i++)
        #pragma unroll
        for (int j = 0; j < 4; j++)
            #pragma unroll
            for (int r = 0; r < 4; r++) c[i][j][r] = 0.f;

    auto copy_stage = [&](int s) {
        const uint32_t sb = smem_base + (s & 1) * STG;
        const int k0 = s * 32;
        #pragma unroll
        for (int i = 0; i < 2; i++) {
            const int idx = tid + i * 256;
            const int row = idx >> 2, cc = idx & 3;
            const uint32_t soff = (row << 6) + ((cc ^ ((row >> 1) & 3)) << 4);
            const size_t ga = (size_t)(m0 + row) * EDIM + k0 + cc * 8;
            const size_t gb = (size_t)(nbase + row) * EDIM + k0 + cc * 8;
            cp_async16(sb + OFF_AHI + soff, g_a_hi + ga);
            cp_async16(sb + OFF_ALO + soff, g_a_lo + ga);
            cp_async16(sb + OFF_BHI + soff, g_b_hi + gb);
            cp_async16(sb + OFF_BLO + soff, g_b_lo + gb);
        }
        asm volatile("cp.async.commit_group;" ::: "memory");
    };

    copy_stage(0);

    for (int ch = 0; ch < NCHUNK; ch++) {
        if (ch + 1 < NCHUNK) {
            copy_stage(ch + 1);
            asm volatile("cp.async.wait_group 1;" ::: "memory");
        } else {
            asm volatile("cp.async.wait_group 0;" ::: "memory");
        }
        __syncthreads();

        const uint32_t sb = smem_base + (ch & 1) * STG;
        #pragma unroll
        for (int ks = 0; ks < 2; ks++) {
            uint32_t bh[4][2], bl[4][2], a[4][4];
            #pragma unroll
            for (int j2 = 0; j2 < 2; j2++) {
                const int rowB = nw + j2 * 16 + ((quad >> 1) << 3) + lane7;
                const int kcB  = 2 * ks + (quad & 1);
                uint32_t r[4];
                ldsm4(r, sw_addr(sb + OFF_BHI, rowB, kcB));
                bh[2*j2][0] = r[0]; bh[2*j2][1] = r[1];
                bh[2*j2+1][0] = r[2]; bh[2*j2+1][1] = r[3];
                ldsm4(r, sw_addr(sb + OFF_BLO, rowB, kcB));
                bl[2*j2][0] = r[0]; bl[2*j2][1] = r[1];
                bl[2*j2+1][0] = r[2]; bl[2*j2+1][1] = r[3];
            }
            const int rowA_ = ((quad & 1) << 3) + lane7;
            const int kcA   = 2 * ks + (quad >> 1);
            #pragma unroll
            for (int i = 0; i < 4; i++)
                ldsm4(a[i], sw_addr(sb + OFF_AHI, mw + 16 * i + rowA_, kcA));
            #pragma unroll
            for (int i = 0; i < 4; i++)
                #pragma unroll
                for (int j = 0; j < 4; j++) {
                    mma16816(c[i][j], a[i], bh[j]);
                    mma16816(c[i][j], a[i], bl[j]);
                }
            #pragma unroll
            for (int i = 0; i < 4; i++)
                ldsm4(a[i], sw_addr(sb + OFF_ALO, mw + 16 * i + rowA_, kcA));
            #pragma unroll
            for (int i = 0; i < 4; i++)
                #pragma unroll
                for (int j = 0; j < 4; j++)
                    mma16816(c[i][j], a[i], bh[j]);
        }
        __syncthreads();
    }

    // ---- epilogue: bias+scale; q,k -> packed bf16 hi/lo; v -> fp32 ----
    const int which = blockIdx.x / 6;
    const int ncol_off = which * EDIM;
    const float* bias = (which == 0) ? bq : ((which == 1) ? bk : bv);
    const float scale = (which == 0) ? 0.20412414523193154f : 1.0f;
    __nv_bfloat16* dsth = (which == 0) ? g_qh : g_kh;
    __nv_bfloat16* dstl = (which == 0) ? g_ql : g_kl;
    const int g  = lane >> 2;
    const int t4 = lane & 3;

    #pragma unroll
    for (int i = 0; i < 4; i++) {
        #pragma unroll
        for (int half = 0; half < 2; half++) {
            const int row = m0 + mw + 16 * i + g + 8 * half;
            const int bb = row >> 8, tt = row & 255;
            #pragma unroll
            for (int j = 0; j < 4; j++) {
                const int col = nbase + nw + 8 * j + 2 * t4 - ncol_off;
                float2 v;
                v.x = (c[i][j][2*half + 0] + bias[col])     * scale;
                v.y = (c[i][j][2*half + 1] + bias[col + 1]) * scale;
                if (which == 2) {
                    *(float2*)&g_v[(size_t)row * EDIM + col] = v;
                } else {
                    const int h = col / DDIM, d = col - h * DDIM;
                    const size_t off = ((size_t)(bb * HDIM + h) * SDIM + tt) * 32 + d;
                    __nv_bfloat16 hx = __float2bfloat16(v.x);
                    __nv_bfloat16 hy = __float2bfloat16(v.y);
                    __nv_bfloat16 lx = __float2bfloat16(v.x - __bfloat162float(hx));
                    __nv_bfloat16 ly = __float2bfloat16(v.y - __bfloat162float(hy));
                    *(__nv_bfloat162*)&dsth[off] = __nv_bfloat162(hx, hy);
                    *(__nv_bfloat162*)&dstl[off] = __nv_bfloat162(lx, ly);
                }
            }
        }
    }
}

// ---------------- vproj ----------------
__global__ __launch_bounds__(256) void vproj_kernel(
    const float* __restrict__ Wfx, const float* __restrict__ Wfy, const float* __restrict__ Wfz)
{
    const int row = blockIdx.x * 8 + (threadIdx.x >> 5);
    const int h   = threadIdx.x & 31;
    const float* v  = g_v + (size_t)row * EDIM + h * DDIM;
    const float* wx = Wfx + h * DDIM;
    const float* wy = Wfy + h * DDIM;
    const float* wz = Wfz + h * DDIM;
    float vx = 0.f, vy = 0.f, vz = 0.f;
    #pragma unroll
    for (int i = 0; i < 6; i++) {
        float4 vv = *(const float4*)(v  + 4 * i);
        float4 ax = *(const float4*)(wx + 4 * i);
        float4 ay = *(const float4*)(wy + 4 * i);
        float4 az = *(const float4*)(wz + 4 * i);
        vx += vv.x*ax.x + vv.y*ax.y + vv.z*ax.z + vv.w*ax.w;
        vy += vv.x*ay.x + vv.y*ay.y + vv.z*ay.z + vv.w*ay.w;
        vz += vv.x*az.x + vv.y*az.y + vv.z*az.z + vv.w*az.w;
    }
    const int b = row >> 8, t = row & 255;
    *(float4*)&g_vp[((size_t)(b * HDIM + h) * SDIM + t) * 4] = make_float4(vx, vy, vz, 0.f);
}

// ---------------- MMA attention, cp.async-staged, head-pipelined ----------------
// Block = (b, 32 s-rows); 512 threads / 16 warps: mh=wid&1 (16 s-rows), band=wid>>1 (32 t).
#define ABUF  36864     /* per-stage: kh 16K | kl 16K | vp 4K */
#define AZP   73728     /* 2 x 1KB */
#define ARED  75776     /* 3KB */
#define ATTN_SMEM 78848

__global__ __launch_bounds__(512, 1) void attn_kernel(
    const float* __restrict__ attn_bias,
    const float* __restrict__ delta,
    float* __restrict__ out)
{
    extern __shared__ char sa[];
    const uint32_t sb = smem_to_u32(sa);
    const int b   = blockIdx.y;
    const int s0  = blockIdx.x * 32;
    const int tid = threadIdx.x;
    const int lane = tid & 31;
    const int wid  = tid >> 5;
    const int mh   = wid & 1;
    const int band = wid >> 1;
    const int nb   = band * 32;
    const int g    = lane >> 2;
    const int t4   = lane & 3;
    const int l8   = lane & 7, l8h = lane >> 3;

    auto stage = [&](int hh, int pr) {
        const uint32_t kh_s = sb + pr * ABUF;
        const uint32_t kl_s = kh_s + 16384;
        const size_t kbase = (size_t)(b * HDIM + hh) * SDIM * 32;
        #pragma unroll
        for (int i = 0; i < 2; i++) {
            const int m = tid + i * 512;
            const int r = m >> 2, c2 = m & 3;
            const uint32_t so = (r << 6) + ((c2 ^ ((r >> 1) & 3)) << 4);
            cp_async16(kh_s + so, g_kh + kbase + r * 32 + c2 * 8);
            cp_async16(kl_s + so, g_kl + kbase + r * 32 + c2 * 8);
        }
        if (tid < 256)
            cp_async16(kh_s + 32768 + tid * 16,
                       g_vp + (size_t)(b * HDIM + hh) * SDIM * 4 + tid * 4);
        asm volatile("cp.async.commit_group;" ::: "memory");
    };

    float G[2][4][2][3];
    #pragma unroll
    for (int r = 0; r < 2; r++)
        #pragma unroll
        for (int j = 0; j < 4; j++)
            #pragma unroll
            for (int cc = 0; cc < 2; cc++)
                #pragma unroll
                for (int x = 0; x < 3; x++) G[r][j][cc][x] = 0.f;

    stage(0, 0);

    for (int h = 0; h < HDIM; h++) {
        const int par = h & 1;
        __syncthreads();   // prior readers of buffer (1-par) done
        if (h + 1 < HDIM) {
            stage(h + 1, 1 - par);
            asm volatile("cp.async.wait_group 1;" ::: "memory");
        } else {
            asm volatile("cp.async.wait_group 0;" ::: "memory");
        }
        __syncthreads();   // staged data visible

        // q fragments direct from gmem (packed bf16 hi/lo, pad cols are zero)
        const size_t qoff = ((size_t)(b * HDIM + h) * SDIM + s0 + mh * 16) * 32;
        const __nv_bfloat16* qh = g_qh + qoff;
        const __nv_bfloat16* ql = g_ql + qoff;
        uint32_t ah[2][4], al[2][4];
        #pragma unroll
        for (int kk = 0; kk < 2; kk++) {
            const int kb = 16 * kk + 2 * t4;
            ah[kk][0] = *(const uint32_t*)&qh[(g)     * 32 + kb];
            ah[kk][1] = *(const uint32_t*)&qh[(g + 8) * 32 + kb];
            ah[kk][2] = *(const uint32_t*)&qh[(g)     * 32 + kb + 8];
            ah[kk][3] = *(const uint32_t*)&qh[(g + 8) * 32 + kb + 8];
            al[kk][0] = *(const uint32_t*)&ql[(g)     * 32 + kb];
            al[kk][1] = *(const uint32_t*)&ql[(g + 8) * 32 + kb];
            al[kk][2] = *(const uint32_t*)&ql[(g)     * 32 + kb + 8];
            al[kk][3] = *(const uint32_t*)&ql[(g + 8) * 32 + kb + 8];
        }

        const uint32_t kh_s = sb + par * ABUF;
        const uint32_t kl_s = kh_s + 16384;

        float c[4][4];
        #pragma unroll
        for (int j = 0; j < 4; j++)
            #pragma unroll
            for (int r = 0; r < 4; r++) c[j][r] = 0.f;

        #pragma unroll
        for (int j = 0; j < 4; j++) {
            uint32_t bh[4], bl[4];
            const int rowB = nb + j * 8 + l8;
            const uint32_t so = (rowB << 6) + ((l8h ^ ((rowB >> 1) & 3)) << 4);
            ldsm4(bh, kh_s + so);
            ldsm4(bl, kl_s + so);
            mma16816(c[j], ah[0], bh);
            mma16816(c[j], ah[1], bh + 2);
            mma16816(c[j], ah[0], bl);
            mma16816(c[j], ah[1], bl + 2);
            mma16816(c[j], al[0], bh);
            mma16816(c[j], al[1], bh + 2);
        }

        // bias + exp + row partial sums
        const float* bp0 = attn_bias +
            (((size_t)b * HDIM + h) * SDIM + s0 + mh * 16 + g) * SDIM + nb + 2 * t4;
        const float* bp1 = bp0 + 8 * SDIM;
        float ps0 = 0.f, ps1 = 0.f;
        #pragma unroll
        for (int j = 0; j < 4; j++) {
            float2 b0 = *(const float2*)(bp0 + 8 * j);
            float2 b1 = *(const float2*)(bp1 + 8 * j);
            c[j][0] = __expf(c[j][0] + b0.x);
            c[j][1] = __expf(c[j][1] + b0.y);
            c[j][2] = __expf(c[j][2] + b1.x);
            c[j][3] = __expf(c[j][3] + b1.y);
            ps0 += c[j][0] + c[j][1];
            ps1 += c[j][2] + c[j][3];
        }
        ps0 += __shfl_xor_sync(0xffffffffu, ps0, 1);
        ps0 += __shfl_xor_sync(0xffffffffu, ps0, 2);
        ps1 += __shfl_xor_sync(0xffffffffu, ps1, 1);
        ps1 += __shfl_xor_sync(0xffffffffu, ps1, 2);
        float* zp = (float*)(sa + AZP + par * 1024);
        if (t4 == 0) {
            zp[(mh * 16 + g) * 8 + band]     = ps0;
            zp[(mh * 16 + g + 8) * 8 + band] = ps1;
        }
        __syncthreads();

        float Z0, Z1;
        {
            float4 a0 = *(float4*)(zp + (mh * 16 + g) * 8);
            float4 a1 = *(float4*)(zp + (mh * 16 + g) * 8 + 4);
            Z0 = (a0.x + a0.y) + (a0.z + a0.w) + (a1.x + a1.y) + (a1.z + a1.w);
            float4 b0 = *(float4*)(zp + (mh * 16 + g + 8) * 8);
            float4 b1 = *(float4*)(zp + (mh * 16 + g + 8) * 8 + 4);
            Z1 = (b0.x + b0.y) + (b0.z + b0.w) + (b1.x + b1.y) + (b1.z + b1.w);
        }
        const float iz0 = __fdividef(1.f, Z0);
        const float iz1 = __fdividef(1.f, Z1);

        #pragma unroll
        for (int j = 0; j < 4; j++) {
            const char* vpp = sa + par * ABUF + 32768 + (nb + 8 * j + 2 * t4) * 16;
            float4 v0 = *(const float4*)vpp;
            float4 v1 = *(const float4*)(vpp + 16);
            const float p00 = c[j][0] * iz0, p01 = c[j][1] * iz0;
            const float p10 = c[j][2] * iz1, p11 = c[j][3] * iz1;
            G[0][j][0][0] = fmaf(p00, v0.x, G[0][j][0][0]);
            G[0][j][0][1] = fmaf(p00, v0.y, G[0][j][0][1]);
            G[0][j][0][2] = fmaf(p00, v0.z, G[0][j][0][2]);
            G[0][j][1][0] = fmaf(p01, v1.x, G[0][j][1][0]);
            G[0][j][1][1] = fmaf(p01, v1.y, G[0][j][1][1]);
            G[0][j][1][2] = fmaf(p01, v1.z, G[0][j][1][2]);
            G[1][j][0][0] = fmaf(p10, v0.x, G[1][j][0][0]);
            G[1][j][0][1] = fmaf(p10, v0.y, G[1][j][0][1]);
            G[1][j][0][2] = fmaf(p10, v0.z, G[1][j][0][2]);
            G[1][j][1][0] = fmaf(p11, v1.x, G[1][j][1][0]);
            G[1][j][1][1] = fmaf(p11, v1.y, G[1][j][1][1]);
            G[1][j][1][2] = fmaf(p11, v1.z, G[1][j][1][2]);
        }
    }

    // ---- delta contraction + output ----
    float ox[2] = {0.f, 0.f}, oy[2] = {0.f, 0.f}, oz[2] = {0.f, 0.f};
    #pragma unroll
    for (int rh = 0; rh < 2; rh++) {
        const int srow = s0 + mh * 16 + g + 8 * rh;
        const float* dp = delta + (size_t)(b * SDIM + srow) * SDIM * 3;
        #pragma unroll
        for (int j = 0; j < 4; j++) {
            const int t0 = nb + 8 * j + 2 * t4;
            const float* d0 = dp + t0 * 3;
            ox[rh] += G[rh][j][0][0] * d0[0] + G[rh][j][1][0] * d0[3];
            oy[rh] += G[rh][j][0][1] * d0[1] + G[rh][j][1][1] * d0[4];
            oz[rh] += G[rh][j][0][2] * d0[2] + G[rh][j][1][2] * d0[5];
        }
    }
    #pragma unroll
    for (int rh = 0; rh < 2; rh++) {
        ox[rh] += __shfl_xor_sync(0xffffffffu, ox[rh], 1);
        ox[rh] += __shfl_xor_sync(0xffffffffu, ox[rh], 2);
        oy[rh] += __shfl_xor_sync(0xffffffffu, oy[rh], 1);
        oy[rh] += __shfl_xor_sync(0xffffffffu, oy[rh], 2);
        oz[rh] += __shfl_xor_sync(0xffffffffu, oz[rh], 1);
        oz[rh] += __shfl_xor_sync(0xffffffffu, oz[rh], 2);
    }
    float* red = (float*)(sa + ARED);
    if (t4 == 0) {
        #pragma unroll
        for (int rh = 0; rh < 2; rh++) {
            const int row = mh * 16 + g + 8 * rh;
            red[(row * 8 + band) * 3 + 0] = ox[rh];
            red[(row * 8 + band) * 3 + 1] = oy[rh];
            red[(row * 8 + band) * 3 + 2] = oz[rh];
        }
    }
    __syncthreads();
    if (tid < 96) {
        const int row = tid / 3, x = tid % 3;
        float s = 0.f;
        #pragma unroll
        for (int k = 0; k < 8; k++) s += red[(row * 8 + k) * 3 + x];
        out[((size_t)(b * SDIM) + s0 + row) * 3 + x] = s;
    }
}

// ---------------- launch ----------------
extern "C" void kernel_launch(void* const* d_in, const int* in_sizes, int n_in,
                              void* d_out, int out_size)
{
    const float* feats     = (const float*)d_in[0];
    const float* attn_bias = (const float*)d_in[1];
    const float* delta     = (const float*)d_in[2];
    const float* Wq  = (const float*)d_in[3];
    const float* bq  = (const float*)d_in[4];
    const float* Wk  = (const float*)d_in[5];
    const float* bk  = (const float*)d_in[6];
    const float* Wv  = (const float*)d_in[7];
    const float* bv  = (const float*)d_in[8];
    const float* Wfx = (const float*)d_in[9];
    const float* Wfy = (const float*)d_in[10];
    const float* Wfz = (const float*)d_in[11];
    float* out = (float*)d_out;

    prep_a_kernel<<<(ROWS * EDIM / 4) / 256, 256>>>(feats);
    prep_w_kernel<<<dim3(EDIM / 32, EDIM / 32, 3), 256>>>(Wq, Wk, Wv);

    cudaFuncSetAttribute(qkv_mma_kernel, cudaFuncAttributeMaxDynamicSharedMemorySize, GEMM_SMEM);
    dim3 gg(QKVN / 128, ROWS / 128);
    qkv_mma_kernel<<<gg, 256, GEMM_SMEM>>>(bq, bk, bv);

    vproj_kernel<<<ROWS / 8, 256>>>(Wfx, Wfy, Wfz);

    cudaFuncSetAttribute(attn_kernel, cudaFuncAttributeMaxDynamicSharedMemorySize, ATTN_SMEM);
    dim3 g2(SDIM / 32, BDIM);
    attn_kernel<<<g2, 512, ATTN_SMEM>>>(attn_bias, delta, out);
}

// round 7
// speedup vs baseline: 3.3659x; 1.2381x over previous
#include <cuda_runtime.h>
#include <cuda_bf16.h>
#include <cstdint>
#include <math.h>

#define BDIM 32
#define SDIM 256
#define EDIM 768
#define HDIM 32
#define DDIM 24
#define ROWS (BDIM*SDIM)     /* 8192 */
#define QKVN (3*EDIM)        /* 2304 */

// ---------------- device scratch ----------------
__device__ __align__(16) __nv_bfloat16 g_a_hi[(size_t)ROWS * EDIM];
__device__ __align__(16) __nv_bfloat16 g_a_lo[(size_t)ROWS * EDIM];
__device__ __align__(16) __nv_bfloat16 g_b_hi[(size_t)QKVN * EDIM];   // wt[n][k]
__device__ __align__(16) __nv_bfloat16 g_b_lo[(size_t)QKVN * EDIM];
// q/k in attn-ready packed bf16 hi/lo: [b][h][s][32] (cols 24..31 stay zero)
__device__ __align__(16) __nv_bfloat16 g_qh[(size_t)ROWS * HDIM * 32];
__device__ __align__(16) __nv_bfloat16 g_ql[(size_t)ROWS * HDIM * 32];
__device__ __align__(16) __nv_bfloat16 g_kh[(size_t)ROWS * HDIM * 32];
__device__ __align__(16) __nv_bfloat16 g_kl[(size_t)ROWS * HDIM * 32];
__device__ float g_v [(size_t)ROWS * EDIM];
__device__ float g_vp[(size_t)ROWS * HDIM * 4];

// ---------------- PTX helpers (base sm_80+ ISA only) ----------------
__device__ __forceinline__ uint32_t smem_to_u32(const void* p) {
    uint32_t a;
    asm("{ .reg .u64 t; cvta.to.shared.u64 t, %1; cvt.u32.u64 %0, t; }" : "=r"(a) : "l"(p));
    return a;
}
__device__ __forceinline__ void cp_async16(uint32_t s, const void* g) {
    asm volatile("cp.async.cg.shared.global [%0], [%1], 16;" :: "r"(s), "l"(g) : "memory");
}
__device__ __forceinline__ void ldsm4(uint32_t* r, uint32_t addr) {
    asm volatile("ldmatrix.sync.aligned.m8n8.x4.shared.b16 {%0,%1,%2,%3}, [%4];"
                 : "=r"(r[0]), "=r"(r[1]), "=r"(r[2]), "=r"(r[3]) : "r"(addr));
}
__device__ __forceinline__ void mma16816(float* c, const uint32_t* a, const uint32_t* b) {
    asm volatile("mma.sync.aligned.m16n8k16.row.col.f32.bf16.bf16.f32 "
                 "{%0,%1,%2,%3}, {%4,%5,%6,%7}, {%8,%9}, {%0,%1,%2,%3};"
                 : "+f"(c[0]), "+f"(c[1]), "+f"(c[2]), "+f"(c[3])
                 : "r"(a[0]), "r"(a[1]), "r"(a[2]), "r"(a[3]), "r"(b[0]), "r"(b[1]));
}

// ---------------- prep: feats -> bf16 hi/lo ----------------
__global__ __launch_bounds__(256) void prep_a_kernel(const float* __restrict__ feats)
{
    const size_t i = (size_t)blockIdx.x * 256 + threadIdx.x;
    float4 v = ((const float4*)feats)[i];
    __nv_bfloat16 hx = __float2bfloat16(v.x), hy = __float2bfloat16(v.y);
    __nv_bfloat16 hz = __float2bfloat16(v.z), hw = __float2bfloat16(v.w);
    __nv_bfloat16 lx = __float2bfloat16(v.x - __bfloat162float(hx));
    __nv_bfloat16 ly = __float2bfloat16(v.y - __bfloat162float(hy));
    __nv_bfloat16 lz = __float2bfloat16(v.z - __bfloat162float(hz));
    __nv_bfloat16 lw = __float2bfloat16(v.w - __bfloat162float(hw));
    __nv_bfloat162* ph = (__nv_bfloat162*)g_a_hi;
    __nv_bfloat162* pl = (__nv_bfloat162*)g_a_lo;
    ph[2*i]   = __nv_bfloat162(hx, hy); ph[2*i+1] = __nv_bfloat162(hz, hw);
    pl[2*i]   = __nv_bfloat162(lx, ly); pl[2*i+1] = __nv_bfloat162(lz, lw);
}

// ---------------- prep: weights transpose + split ----------------
__global__ __launch_bounds__(256) void prep_w_kernel(
    const float* __restrict__ Wq, const float* __restrict__ Wk, const float* __restrict__ Wv)
{
    __shared__ float tile[32][33];
    const int which = blockIdx.z;
    const float* W = (which == 0) ? Wq : ((which == 1) ? Wk : Wv);
    const int n0 = blockIdx.x * 32, k0 = blockIdx.y * 32;
    const int tx = threadIdx.x & 31, ty = (threadIdx.x >> 5) * 4;
    #pragma unroll
    for (int i = 0; i < 4; i++)
        tile[ty + i][tx] = W[(size_t)(k0 + ty + i) * EDIM + n0 + tx];
    __syncthreads();
    #pragma unroll
    for (int i = 0; i < 4; i++) {
        const int n = n0 + ty + i, k = k0 + tx;
        const float v = tile[tx][ty + i];
        __nv_bfloat16 h = __float2bfloat16(v);
        __nv_bfloat16 l = __float2bfloat16(v - __bfloat162float(h));
        g_b_hi[(size_t)(which * EDIM + n) * EDIM + k] = h;
        g_b_lo[(size_t)(which * EDIM + n) * EDIM + k] = l;
    }
}

// ---------------- HMMA QKV GEMM: 3-stage pipeline, 1 barrier/chunk ----------------
#define OFF_AHI 0
#define OFF_ALO 8192
#define OFF_BHI 16384
#define OFF_BLO 24576
#define STG 32768
#define GEMM_SMEM (3*STG)
#define NCHUNK (EDIM/32)

__device__ __forceinline__ uint32_t sw_addr(uint32_t tile, int row, int kc) {
    return tile + (row << 6) + ((kc ^ ((row >> 1) & 3)) << 4);
}

__global__ __launch_bounds__(256, 2) void qkv_mma_kernel(
    const float* __restrict__ bq, const float* __restrict__ bk, const float* __restrict__ bv)
{
    extern __shared__ char smem[];
    const uint32_t smem_base = smem_to_u32(smem);
    const int tid  = threadIdx.x;
    const int wid  = tid >> 5;
    const int lane = tid & 31;
    const int m0    = blockIdx.y * 128;
    const int nbase = blockIdx.x * 128;

    const int wm = wid & 1, wn = wid >> 1;
    const int mw = wm * 64, nw = wn * 32;
    const int lane7 = lane & 7, quad = lane >> 3;

    float c[4][4][4];
    #pragma unroll
    for (int i = 0; i < 4; i++)
        #pragma unroll
        for (int j = 0; j < 4; j++)
            #pragma unroll
            for (int r = 0; r < 4; r++) c[i][j][r] = 0.f;

    auto copy_stage = [&](int s) {
        const uint32_t sb = smem_base + (s % 3) * STG;
        const int k0 = s * 32;
        #pragma unroll
        for (int i = 0; i < 2; i++) {
            const int idx = tid + i * 256;
            const int row = idx >> 2, cc = idx & 3;
            const uint32_t soff = (row << 6) + ((cc ^ ((row >> 1) & 3)) << 4);
            const size_t ga = (size_t)(m0 + row) * EDIM + k0 + cc * 8;
            const size_t gb = (size_t)(nbase + row) * EDIM + k0 + cc * 8;
            cp_async16(sb + OFF_AHI + soff, g_a_hi + ga);
            cp_async16(sb + OFF_ALO + soff, g_a_lo + ga);
            cp_async16(sb + OFF_BHI + soff, g_b_hi + gb);
            cp_async16(sb + OFF_BLO + soff, g_b_lo + gb);
        }
        asm volatile("cp.async.commit_group;" ::: "memory");
    };

    copy_stage(0);
    copy_stage(1);

    for (int ch = 0; ch < NCHUNK; ch++) {
        if (ch + 1 < NCHUNK) {
            asm volatile("cp.async.wait_group 1;" ::: "memory");
        } else {
            asm volatile("cp.async.wait_group 0;" ::: "memory");
        }
        __syncthreads();   // stage ch visible; all warps done with ch-1's buffer
        if (ch + 2 < NCHUNK) copy_stage(ch + 2);   // fills buffer (ch-1)%3, now free

        const uint32_t sb = smem_base + (ch % 3) * STG;
        #pragma unroll
        for (int ks = 0; ks < 2; ks++) {
            uint32_t bh[4][2], bl[4][2], a[4][4];
            #pragma unroll
            for (int j2 = 0; j2 < 2; j2++) {
                const int rowB = nw + j2 * 16 + ((quad >> 1) << 3) + lane7;
                const int kcB  = 2 * ks + (quad & 1);
                uint32_t r[4];
                ldsm4(r, sw_addr(sb + OFF_BHI, rowB, kcB));
                bh[2*j2][0] = r[0]; bh[2*j2][1] = r[1];
                bh[2*j2+1][0] = r[2]; bh[2*j2+1][1] = r[3];
                ldsm4(r, sw_addr(sb + OFF_BLO, rowB, kcB));
                bl[2*j2][0] = r[0]; bl[2*j2][1] = r[1];
                bl[2*j2+1][0] = r[2]; bl[2*j2+1][1] = r[3];
            }
            const int rowA_ = ((quad & 1) << 3) + lane7;
            const int kcA   = 2 * ks + (quad >> 1);
            #pragma unroll
            for (int i = 0; i < 4; i++)
                ldsm4(a[i], sw_addr(sb + OFF_AHI, mw + 16 * i + rowA_, kcA));
            #pragma unroll
            for (int i = 0; i < 4; i++)
                #pragma unroll
                for (int j = 0; j < 4; j++) {
                    mma16816(c[i][j], a[i], bh[j]);
                    mma16816(c[i][j], a[i], bl[j]);
                }
            #pragma unroll
            for (int i = 0; i < 4; i++)
                ldsm4(a[i], sw_addr(sb + OFF_ALO, mw + 16 * i + rowA_, kcA));
            #pragma unroll
            for (int i = 0; i < 4; i++)
                #pragma unroll
                for (int j = 0; j < 4; j++)
                    mma16816(c[i][j], a[i], bh[j]);
        }
        __syncthreads();   // readers done before next iteration's copy into this region
    }

    // ---- epilogue ----
    const int which = blockIdx.x / 6;
    const int ncol_off = which * EDIM;
    const float* bias = (which == 0) ? bq : ((which == 1) ? bk : bv);
    const float scale = (which == 0) ? 0.20412414523193154f : 1.0f;
    __nv_bfloat16* dsth = (which == 0) ? g_qh : g_kh;
    __nv_bfloat16* dstl = (which == 0) ? g_ql : g_kl;
    const int g  = lane >> 2;
    const int t4 = lane & 3;

    #pragma unroll
    for (int i = 0; i < 4; i++) {
        #pragma unroll
        for (int half = 0; half < 2; half++) {
            const int row = m0 + mw + 16 * i + g + 8 * half;
            const int bb = row >> 8, tt = row & 255;
            #pragma unroll
            for (int j = 0; j < 4; j++) {
                const int col = nbase + nw + 8 * j + 2 * t4 - ncol_off;
                float2 v;
                v.x = (c[i][j][2*half + 0] + bias[col])     * scale;
                v.y = (c[i][j][2*half + 1] + bias[col + 1]) * scale;
                if (which == 2) {
                    *(float2*)&g_v[(size_t)row * EDIM + col] = v;
                } else {
                    const int h = col / DDIM, d = col - h * DDIM;
                    const size_t off = ((size_t)(bb * HDIM + h) * SDIM + tt) * 32 + d;
                    __nv_bfloat16 hx = __float2bfloat16(v.x);
                    __nv_bfloat16 hy = __float2bfloat16(v.y);
                    __nv_bfloat16 lx = __float2bfloat16(v.x - __bfloat162float(hx));
                    __nv_bfloat16 ly = __float2bfloat16(v.y - __bfloat162float(hy));
                    *(__nv_bfloat162*)&dsth[off] = __nv_bfloat162(hx, hy);
                    *(__nv_bfloat162*)&dstl[off] = __nv_bfloat162(lx, ly);
                }
            }
        }
    }
}

// ---------------- vproj ----------------
__global__ __launch_bounds__(256) void vproj_kernel(
    const float* __restrict__ Wfx, const float* __restrict__ Wfy, const float* __restrict__ Wfz)
{
    const int row = blockIdx.x * 8 + (threadIdx.x >> 5);
    const int h   = threadIdx.x & 31;
    const float* v  = g_v + (size_t)row * EDIM + h * DDIM;
    const float* wx = Wfx + h * DDIM;
    const float* wy = Wfy + h * DDIM;
    const float* wz = Wfz + h * DDIM;
    float vx = 0.f, vy = 0.f, vz = 0.f;
    #pragma unroll
    for (int i = 0; i < 6; i++) {
        float4 vv = *(const float4*)(v  + 4 * i);
        float4 ax = *(const float4*)(wx + 4 * i);
        float4 ay = *(const float4*)(wy + 4 * i);
        float4 az = *(const float4*)(wz + 4 * i);
        vx += vv.x*ax.x + vv.y*ax.y + vv.z*ax.z + vv.w*ax.w;
        vy += vv.x*ay.x + vv.y*ay.y + vv.z*ay.z + vv.w*ay.w;
        vz += vv.x*az.x + vv.y*az.y + vv.z*az.z + vv.w*az.w;
    }
    const int b = row >> 8, t = row & 255;
    *(float4*)&g_vp[((size_t)(b * HDIM + h) * SDIM + t) * 4] = make_float4(vx, vy, vz, 0.f);
}

// ---------------- MMA attention: k+vp+BIAS all cp.async staged ----------------
// Block = (b, 32 s-rows); 512 threads / 16 warps: mh=wid&1 (16 s-rows), band=wid>>1 (32 t).
// Stage layout: KH 16K | KL 16K | VP 4K | BIAS 32x1040B; two stages.
#define AKH   0
#define AKL   16384
#define AVP   32768
#define ABIA  36864
#define BROW  1040
#define ASTG  70400     /* 36864 + 32*1040 = 70144, rounded to 128 */
#define AZP   (2*ASTG)           /* 2KB */
#define ARED  (2*ASTG + 2048)    /* 3KB */
#define ATTN_SMEM (2*ASTG + 2048 + 3072)

__global__ __launch_bounds__(512, 1) void attn_kernel(
    const float* __restrict__ attn_bias,
    const float* __restrict__ delta,
    float* __restrict__ out)
{
    extern __shared__ char sa[];
    const uint32_t sb = smem_to_u32(sa);
    const int b   = blockIdx.y;
    const int s0  = blockIdx.x * 32;
    const int tid = threadIdx.x;
    const int lane = tid & 31;
    const int wid  = tid >> 5;
    const int mh   = wid & 1;
    const int band = wid >> 1;
    const int nb   = band * 32;
    const int g    = lane >> 2;
    const int t4   = lane & 3;
    const int l8   = lane & 7, l8h = lane >> 3;

    auto stage = [&](int hh, int pr) {
        const uint32_t bufs = sb + pr * ASTG;
        const size_t kbase = (size_t)(b * HDIM + hh) * SDIM * 32;
        #pragma unroll
        for (int i = 0; i < 2; i++) {
            const int m = tid + i * 512;
            const int r = m >> 2, c2 = m & 3;
            const uint32_t so = (r << 6) + ((c2 ^ ((r >> 1) & 3)) << 4);
            cp_async16(bufs + AKH + so, g_kh + kbase + r * 32 + c2 * 8);
            cp_async16(bufs + AKL + so, g_kl + kbase + r * 32 + c2 * 8);
        }
        if (tid < 256)
            cp_async16(bufs + AVP + tid * 16,
                       g_vp + (size_t)(b * HDIM + hh) * SDIM * 4 + tid * 4);
        const float* bsrc = attn_bias + (((size_t)b * HDIM + hh) * SDIM + s0) * SDIM;
        #pragma unroll
        for (int i = 0; i < 4; i++) {
            const int m = tid + i * 512;            // 0..2047
            const int r = m >> 6, cc = m & 63;
            cp_async16(bufs + ABIA + r * BROW + cc * 16, bsrc + (size_t)r * SDIM + cc * 4);
        }
        asm volatile("cp.async.commit_group;" ::: "memory");
    };

    float G[2][4][2][3];
    #pragma unroll
    for (int r = 0; r < 2; r++)
        #pragma unroll
        for (int j = 0; j < 4; j++)
            #pragma unroll
            for (int cc = 0; cc < 2; cc++)
                #pragma unroll
                for (int x = 0; x < 3; x++) G[r][j][cc][x] = 0.f;

    stage(0, 0);

    for (int h = 0; h < HDIM; h++) {
        const int par = h & 1;
        asm volatile("cp.async.wait_group 0;" ::: "memory");
        __syncthreads();    // stage h visible; buffer 1-par free (prior head done)
        if (h + 1 < HDIM) stage(h + 1, 1 - par);

        // q fragments direct from gmem (packed bf16 hi/lo, pad cols are zero)
        const size_t qoff = ((size_t)(b * HDIM + h) * SDIM + s0 + mh * 16) * 32;
        const __nv_bfloat16* qh = g_qh + qoff;
        const __nv_bfloat16* ql = g_ql + qoff;
        uint32_t ah[2][4], al[2][4];
        #pragma unroll
        for (int kk = 0; kk < 2; kk++) {
            const int kb = 16 * kk + 2 * t4;
            ah[kk][0] = *(const uint32_t*)&qh[(g)     * 32 + kb];
            ah[kk][1] = *(const uint32_t*)&qh[(g + 8) * 32 + kb];
            ah[kk][2] = *(const uint32_t*)&qh[(g)     * 32 + kb + 8];
            ah[kk][3] = *(const uint32_t*)&qh[(g + 8) * 32 + kb + 8];
            al[kk][0] = *(const uint32_t*)&ql[(g)     * 32 + kb];
            al[kk][1] = *(const uint32_t*)&ql[(g + 8) * 32 + kb];
            al[kk][2] = *(const uint32_t*)&ql[(g)     * 32 + kb + 8];
            al[kk][3] = *(const uint32_t*)&ql[(g + 8) * 32 + kb + 8];
        }

        const uint32_t bufs = sb + par * ASTG;

        float c[4][4];
        #pragma unroll
        for (int j = 0; j < 4; j++)
            #pragma unroll
            for (int r = 0; r < 4; r++) c[j][r] = 0.f;

        #pragma unroll
        for (int j = 0; j < 4; j++) {
            uint32_t bh[4], bl[4];
            const int rowB = nb + j * 8 + l8;
            const uint32_t so = (rowB << 6) + ((l8h ^ ((rowB >> 1) & 3)) << 4);
            ldsm4(bh, bufs + AKH + so);
            ldsm4(bl, bufs + AKL + so);
            mma16816(c[j], ah[0], bh);
            mma16816(c[j], ah[1], bh + 2);
            mma16816(c[j], ah[0], bl);
            mma16816(c[j], ah[1], bl + 2);
            mma16816(c[j], al[0], bh);
            mma16816(c[j], al[1], bh + 2);
        }

        // bias (smem) + exp + row partial sums
        const char* bp0 = sa + par * ASTG + ABIA + (mh * 16 + g) * BROW + (nb + 2 * t4) * 4;
        const char* bp1 = bp0 + 8 * BROW;
        float ps0 = 0.f, ps1 = 0.f;
        #pragma unroll
        for (int j = 0; j < 4; j++) {
            float2 b0 = *(const float2*)(bp0 + 32 * j);
            float2 b1 = *(const float2*)(bp1 + 32 * j);
            c[j][0] = __expf(c[j][0] + b0.x);
            c[j][1] = __expf(c[j][1] + b0.y);
            c[j][2] = __expf(c[j][2] + b1.x);
            c[j][3] = __expf(c[j][3] + b1.y);
            ps0 += c[j][0] + c[j][1];
            ps1 += c[j][2] + c[j][3];
        }
        ps0 += __shfl_xor_sync(0xffffffffu, ps0, 1);
        ps0 += __shfl_xor_sync(0xffffffffu, ps0, 2);
        ps1 += __shfl_xor_sync(0xffffffffu, ps1, 1);
        ps1 += __shfl_xor_sync(0xffffffffu, ps1, 2);
        float* zp = (float*)(sa + AZP + par * 1024);
        if (t4 == 0) {
            zp[(mh * 16 + g) * 8 + band]     = ps0;
            zp[(mh * 16 + g + 8) * 8 + band] = ps1;
        }
        __syncthreads();

        float Z0, Z1;
        {
            float4 a0 = *(float4*)(zp + (mh * 16 + g) * 8);
            float4 a1 = *(float4*)(zp + (mh * 16 + g) * 8 + 4);
            Z0 = (a0.x + a0.y) + (a0.z + a0.w) + (a1.x + a1.y) + (a1.z + a1.w);
            float4 b0 = *(float4*)(zp + (mh * 16 + g + 8) * 8);
            float4 b1 = *(float4*)(zp + (mh * 16 + g + 8) * 8 + 4);
            Z1 = (b0.x + b0.y) + (b0.z + b0.w) + (b1.x + b1.y) + (b1.z + b1.w);
        }
        const float iz0 = __fdividef(1.f, Z0);
        const float iz1 = __fdividef(1.f, Z1);

        #pragma unroll
        for (int j = 0; j < 4; j++) {
            const char* vpp = sa + par * ASTG + AVP + (nb + 8 * j + 2 * t4) * 16;
            float4 v0 = *(const float4*)vpp;
            float4 v1 = *(const float4*)(vpp + 16);
            const float p00 = c[j][0] * iz0, p01 = c[j][1] * iz0;
            const float p10 = c[j][2] * iz1, p11 = c[j][3] * iz1;
            G[0][j][0][0] = fmaf(p00, v0.x, G[0][j][0][0]);
            G[0][j][0][1] = fmaf(p00, v0.y, G[0][j][0][1]);
            G[0][j][0][2] = fmaf(p00, v0.z, G[0][j][0][2]);
            G[0][j][1][0] = fmaf(p01, v1.x, G[0][j][1][0]);
            G[0][j][1][1] = fmaf(p01, v1.y, G[0][j][1][1]);
            G[0][j][1][2] = fmaf(p01, v1.z, G[0][j][1][2]);
            G[1][j][0][0] = fmaf(p10, v0.x, G[1][j][0][0]);
            G[1][j][0][1] = fmaf(p10, v0.y, G[1][j][0][1]);
            G[1][j][0][2] = fmaf(p10, v0.z, G[1][j][0][2]);
            G[1][j][1][0] = fmaf(p11, v1.x, G[1][j][1][0]);
            G[1][j][1][1] = fmaf(p11, v1.y, G[1][j][1][1]);
            G[1][j][1][2] = fmaf(p11, v1.z, G[1][j][1][2]);
        }
    }

    // ---- delta contraction + output ----
    float ox[2] = {0.f, 0.f}, oy[2] = {0.f, 0.f}, oz[2] = {0.f, 0.f};
    #pragma unroll
    for (int rh = 0; rh < 2; rh++) {
        const int srow = s0 + mh * 16 + g + 8 * rh;
        const float* dp = delta + (size_t)(b * SDIM + srow) * SDIM * 3;
        #pragma unroll
        for (int j = 0; j < 4; j++) {
            const int t0 = nb + 8 * j + 2 * t4;
            const float* d0 = dp + t0 * 3;
            ox[rh] += G[rh][j][0][0] * d0[0] + G[rh][j][1][0] * d0[3];
            oy[rh] += G[rh][j][0][1] * d0[1] + G[rh][j][1][1] * d0[4];
            oz[rh] += G[rh][j][0][2] * d0[2] + G[rh][j][1][2] * d0[5];
        }
    }
    #pragma unroll
    for (int rh = 0; rh < 2; rh++) {
        ox[rh] += __shfl_xor_sync(0xffffffffu, ox[rh], 1);
        ox[rh] += __shfl_xor_sync(0xffffffffu, ox[rh], 2);
        oy[rh] += __shfl_xor_sync(0xffffffffu, oy[rh], 1);
        oy[rh] += __shfl_xor_sync(0xffffffffu, oy[rh], 2);
        oz[rh] += __shfl_xor_sync(0xffffffffu, oz[rh], 1);
        oz[rh] += __shfl_xor_sync(0xffffffffu, oz[rh], 2);
    }
    float* red = (float*)(sa + ARED);
    if (t4 == 0) {
        #pragma unroll
        for (int rh = 0; rh < 2; rh++) {
            const int row = mh * 16 + g + 8 * rh;
            red[(row * 8 + band) * 3 + 0] = ox[rh];
            red[(row * 8 + band) * 3 + 1] = oy[rh];
            red[(row * 8 + band) * 3 + 2] = oz[rh];
        }
    }
    __syncthreads();
    if (tid < 96) {
        const int row = tid / 3, x = tid % 3;
        float s = 0.f;
        #pragma unroll
        for (int k = 0; k < 8; k++) s += red[(row * 8 + k) * 3 + x];
        out[((size_t)(b * SDIM) + s0 + row) * 3 + x] = s;
    }
}

// ---------------- launch ----------------
extern "C" void kernel_launch(void* const* d_in, const int* in_sizes, int n_in,
                              void* d_out, int out_size)
{
    const float* feats     = (const float*)d_in[0];
    const float* attn_bias = (const float*)d_in[1];
    const float* delta     = (const float*)d_in[2];
    const float* Wq  = (const float*)d_in[3];
    const float* bq  = (const float*)d_in[4];
    const float* Wk  = (const float*)d_in[5];
    const float* bk  = (const float*)d_in[6];
    const float* Wv  = (const float*)d_in[7];
    const float* bv  = (const float*)d_in[8];
    const float* Wfx = (const float*)d_in[9];
    const float* Wfy = (const float*)d_in[10];
    const float* Wfz = (const float*)d_in[11];
    float* out = (float*)d_out;

    prep_a_kernel<<<(ROWS * EDIM / 4) / 256, 256>>>(feats);
    prep_w_kernel<<<dim3(EDIM / 32, EDIM / 32, 3), 256>>>(Wq, Wk, Wv);

    cudaFuncSetAttribute(qkv_mma_kernel, cudaFuncAttributeMaxDynamicSharedMemorySize, GEMM_SMEM);
    dim3 gg(QKVN / 128, ROWS / 128);
    qkv_mma_kernel<<<gg, 256, GEMM_SMEM>>>(bq, bk, bv);

    vproj_kernel<<<ROWS / 8, 256>>>(Wfx, Wfy, Wfz);

    cudaFuncSetAttribute(attn_kernel, cudaFuncAttributeMaxDynamicSharedMemorySize, ATTN_SMEM);
    dim3 g2(SDIM / 32, BDIM);
    attn_kernel<<<g2, 512, ATTN_SMEM>>>(attn_bias, delta, out);
}